// round 12
// baseline (speedup 1.0000x reference)
#include <cuda_runtime.h>
#include <cuda_fp16.h>
#include <math.h>
#include <stdint.h>

#define BATCH   16
#define SEQ     512
#define DMODEL  1024
#define NHEAD   16
#define DK      64
#define FFN_DIM 4096
#define ROWS    (BATCH * SEQ)        // 8192
#define QKV_N   (3 * DMODEL)         // 3072

// ---------------- scratch (device globals; no allocation) ----------------
__device__ __half g_h   [ROWS * DMODEL];
__device__ __half g_qkv [ROWS * QKV_N];
__device__ __half g_att [ROWS * DMODEL];
__device__ float  g_x1  [ROWS * DMODEL];
__device__ __half g_ffn [ROWS * FFN_DIM];
// transposed fp16 weights: T[N,K]
__device__ __half g_wqkvT[QKV_N*DMODEL];
__device__ __half g_woT  [DMODEL*DMODEL];
__device__ __half g_w1T  [DMODEL*FFN_DIM];
__device__ __half g_w2T  [FFN_DIM*DMODEL];

// ---------------- helpers ----------------
__device__ __forceinline__ uint32_t smem_u32(const void* p) {
    uint32_t a;
    asm("{ .reg .u64 t; cvta.to.shared.u64 t, %1; cvt.u32.u64 %0, t; }" : "=r"(a) : "l"(p));
    return a;
}
#define CP_ASYNC16(dst, src) \
    asm volatile("cp.async.cg.shared.global [%0], [%1], 16;" :: "r"(dst), "l"(src) : "memory")
#define CP_COMMIT() asm volatile("cp.async.commit_group;" ::: "memory")
#define CP_WAIT(n)  asm volatile("cp.async.wait_group %0;" :: "n"(n) : "memory")
#define SMEM_SWZ128(off) ((off) ^ (((off) >> 3) & 0x70))

__device__ __forceinline__ void ldsm_x4(uint32_t* r, uint32_t addr) {
    asm volatile("ldmatrix.sync.aligned.m8n8.x4.shared.b16 {%0,%1,%2,%3}, [%4];"
        : "=r"(r[0]), "=r"(r[1]), "=r"(r[2]), "=r"(r[3]) : "r"(addr));
}
__device__ __forceinline__ void ldsm_x4_t(uint32_t* r, uint32_t addr) {
    asm volatile("ldmatrix.sync.aligned.m8n8.x4.trans.shared.b16 {%0,%1,%2,%3}, [%4];"
        : "=r"(r[0]), "=r"(r[1]), "=r"(r[2]), "=r"(r[3]) : "r"(addr));
}
__device__ __forceinline__ void mma16816(float* d, const uint32_t* a, const uint32_t* b) {
    asm volatile("mma.sync.aligned.m16n8k16.row.col.f32.f16.f16.f32 "
        "{%0,%1,%2,%3}, {%4,%5,%6,%7}, {%8,%9}, {%0,%1,%2,%3};"
        : "+f"(d[0]), "+f"(d[1]), "+f"(d[2]), "+f"(d[3])
        : "r"(a[0]), "r"(a[1]), "r"(a[2]), "r"(a[3]), "r"(b[0]), "r"(b[1]));
}

__device__ __forceinline__ float gelu_exact(float v) {
    return 0.5f * v * (1.0f + erff(v * 0.70710678118654752f));
}
__device__ __forceinline__ uint32_t pack2h(__half a, __half b) {
    __half2 t(a, b);
    return *reinterpret_cast<uint32_t*>(&t);
}

// ---------------- fused weight transpose + fp16 quantize ----------------
struct WArgs {
    const float* W[3];
    __half*      T[3];
    int K[3], N[3], tiles[3];
};

__global__ void wsplit_all(WArgs a)
{
    __shared__ float t[32][33];
    int idx = blockIdx.x;
    int m = 0;
    if (idx >= a.tiles[0]) { idx -= a.tiles[0]; m = 1; }
    if (m == 1 && idx >= a.tiles[1]) { idx -= a.tiles[1]; m = 2; }
    const float* W = a.W[m];
    __half* T = a.T[m];
    int K = a.K[m], N = a.N[m];
    int ntx = N >> 5;
    int n0 = (idx % ntx) * 32, k0 = (idx / ntx) * 32;

    int tx = threadIdx.x, ty = threadIdx.y;
    #pragma unroll
    for (int i = 0; i < 4; i++)
        t[ty + 8*i][tx] = W[(size_t)(k0 + ty + 8*i) * N + n0 + tx];
    __syncthreads();
    #pragma unroll
    for (int i = 0; i < 4; i++) {
        size_t o = (size_t)(n0 + ty + 8*i) * K + k0 + tx;
        T[o] = __float2half(t[tx][ty + 8*i]);
    }
}

// ---------------- LayerNorm: one block per row, outputs fp16 ----------------
__global__ void ln_kernel(const float* __restrict__ x,
                          const float* __restrict__ g,
                          const float* __restrict__ b,
                          __half* __restrict__ oh)
{
    int row = blockIdx.x;
    const float4* xr = reinterpret_cast<const float4*>(x + (size_t)row * DMODEL);
    int t = threadIdx.x;
    float4 v = xr[t];
    float s  = v.x + v.y + v.z + v.w;
    float sq = v.x*v.x + v.y*v.y + v.z*v.z + v.w*v.w;

    __shared__ float red_s[8], red_q[8];
    for (int o = 16; o > 0; o >>= 1) {
        s  += __shfl_xor_sync(0xffffffffu, s,  o);
        sq += __shfl_xor_sync(0xffffffffu, sq, o);
    }
    int wid = t >> 5, lid = t & 31;
    if (lid == 0) { red_s[wid] = s; red_q[wid] = sq; }
    __syncthreads();
    if (wid == 0) {
        float ss = (lid < 8) ? red_s[lid] : 0.f;
        float qq = (lid < 8) ? red_q[lid] : 0.f;
        for (int o = 4; o > 0; o >>= 1) {
            ss += __shfl_xor_sync(0xffffffffu, ss, o);
            qq += __shfl_xor_sync(0xffffffffu, qq, o);
        }
        if (lid == 0) { red_s[0] = ss; red_q[0] = qq; }
    }
    __syncthreads();
    float mean = red_s[0] * (1.0f / DMODEL);
    float var  = red_q[0] * (1.0f / DMODEL) - mean * mean;
    float rstd = rsqrtf(var + 1e-5f);

    float4 gv = reinterpret_cast<const float4*>(g)[t];
    float4 bv = reinterpret_cast<const float4*>(b)[t];
    float o0 = (v.x - mean) * rstd * gv.x + bv.x;
    float o1 = (v.y - mean) * rstd * gv.y + bv.y;
    float o2 = (v.z - mean) * rstd * gv.z + bv.z;
    float o3 = (v.w - mean) * rstd * gv.w + bv.w;
    __half2* ph = reinterpret_cast<__half2*>(oh + (size_t)row * DMODEL);
    ph[t*2]   = __half2(__float2half(o0), __float2half(o1));
    ph[t*2+1] = __half2(__float2half(o2), __float2half(o3));
}

// ---------------- fp16 GEMM: CTA 128x128, 4 warps 64x64, KBLK=64, 3 stages ----------------
// Cross-barrier register pipeline; barrier every 4 kk-steps (16 per K=1024).
// EPI: 0 = fp16 C; 1 = +bias +resid -> fp32 C; 2 = +bias, GELU -> fp16 C
#define KBLK 64
#define A_ST_BYTES 16384             // 128 rows x 128B
#define STAGE_BYTES 32768            // A 16K | B 16K
#define NSTAGE 3
#define MG_SMEM (NSTAGE * STAGE_BYTES)   // 98304

template<int EPI>
__global__ __launch_bounds__(128, 2)
void mma_gemm(const __half* __restrict__ A, const __half* __restrict__ B,
              const float* __restrict__ bias, const float* __restrict__ resid,
              float* __restrict__ C, __half* __restrict__ Ch,
              int M, int N, int K)
{
    extern __shared__ char sm[];
    uint32_t sb = smem_u32(sm);

    int tid  = threadIdx.x;
    int wid  = tid >> 5;
    int lane = tid & 31;
    int wm   = wid & 1;          // 0..1 (M)
    int wn   = wid >> 1;         // 0..1 (N)

    int row0 = blockIdx.y * 128, col0 = blockIdx.x * 128;
    const __half* pA = A + (size_t)row0 * K;
    const __half* pB = B + (size_t)col0 * K;

    int KB = K / KBLK;

    // cp.async: per tensor 128 rows x 8 chunks(16B) = 1024; 8 chunks/thread
    int ld_r[8], ld_c[8];
    uint32_t ld_so[8];
    #pragma unroll
    for (int i = 0; i < 8; i++) {
        int idx = tid + (i << 7);
        ld_r[i] = idx >> 3;
        ld_c[i] = idx & 7;
        ld_so[i] = SMEM_SWZ128((uint32_t)(ld_r[i] * 128 + ld_c[i] * 16));
    }

    auto stage_base = [&](int kb) {
        return sb + (uint32_t)(kb % NSTAGE) * STAGE_BYTES;
    };

    auto load_stage = [&](int kb) {
        uint32_t base = stage_base(kb);
        int koff = kb * KBLK;
        #pragma unroll
        for (int i = 0; i < 8; i++) {
            size_t go = (size_t)ld_r[i] * K + koff + ld_c[i] * 8;
            CP_ASYNC16(base + ld_so[i],              (const void*)(pA + go));
            CP_ASYNC16(base + A_ST_BYTES + ld_so[i], (const void*)(pB + go));
        }
        CP_COMMIT();
    };

    // fragment load for one kk (k16): A m64 (4 x4) + B n64 (4 x4)
    int a_lane_row = lane & 15;
    int a_lane_c   = ((lane >> 4) << 3) * 2;   // 0 or 16 bytes within k16
    int b_lane_row = ((lane >> 4) << 3) + (lane & 7);
    int b_lane_c   = (((lane >> 3) & 1) << 3) * 2;
    auto ld_frags = [&](uint32_t base, int kk,
                        uint32_t (*ahb)[4], uint32_t (*bhb)[2]) {
        uint32_t sA = base, sB = base + A_ST_BYTES;
        int acol = kk * 32 + a_lane_c;
        #pragma unroll
        for (int mt = 0; mt < 4; mt++) {
            int row = wm * 64 + mt * 16 + a_lane_row;
            uint32_t off = SMEM_SWZ128((uint32_t)(row * 128 + acol));
            ldsm_x4(ahb[mt], sA + off);
        }
        int bcol = kk * 32 + b_lane_c;
        #pragma unroll
        for (int p = 0; p < 4; p++) {
            int brow = wn * 64 + p * 16 + b_lane_row;
            uint32_t off = SMEM_SWZ128((uint32_t)(brow * 128 + bcol));
            uint32_t t[4];
            ldsm_x4(t, sB + off);
            bhb[p*2][0] = t[0]; bhb[p*2][1] = t[1];
            bhb[p*2+1][0] = t[2]; bhb[p*2+1][1] = t[3];
        }
    };

    float acc[4][8][4];
    #pragma unroll
    for (int i = 0; i < 4; i++)
        #pragma unroll
        for (int j = 0; j < 8; j++)
            #pragma unroll
            for (int e = 0; e < 4; e++) acc[i][j][e] = 0.f;

    // prologue: fill 2 stages
    load_stage(0);
    load_stage(1);
    CP_WAIT(1);               // stage 0 landed
    __syncthreads();

    uint32_t ah[2][4][4], bh[2][8][2];
    ld_frags(stage_base(0), 0, ah[0], bh[0]);

    for (int kb = 0; kb < KB; kb++) {
        #pragma unroll
        for (int kk = 0; kk < 4; kk++) {
            int cur = (kb * 4 + kk) & 1;
            int nxt = cur ^ 1;
            if (kk == 3) {
                // all reads of stage kb-1 finished before the PREVIOUS barrier,
                // so overwriting buffer (kb+2)%3 == (kb-1)%3 is safe here.
                if (kb + 2 < KB) load_stage(kb + 2);
                else             CP_COMMIT();
                CP_WAIT(1);      // stage kb+1 landed
                __syncthreads();
                if (kb + 1 < KB)
                    ld_frags(stage_base(kb + 1), 0, ah[nxt], bh[nxt]);
            } else {
                ld_frags(stage_base(kb), kk + 1, ah[nxt], bh[nxt]);
            }
            #pragma unroll
            for (int mt = 0; mt < 4; mt++)
                #pragma unroll
                for (int nt = 0; nt < 8; nt++)
                    mma16816(acc[mt][nt], ah[cur][mt], bh[cur][nt]);
        }
    }

    // epilogue
    int g  = lane >> 2;
    int c2 = (lane & 3) * 2;
    #pragma unroll
    for (int mt = 0; mt < 4; mt++) {
        #pragma unroll
        for (int nt = 0; nt < 8; nt++) {
            int row = row0 + wm * 64 + mt * 16 + g;
            int col = col0 + wn * 64 + nt * 8 + c2;
            float d[4] = {acc[mt][nt][0], acc[mt][nt][1], acc[mt][nt][2], acc[mt][nt][3]};
            if (EPI >= 1) {
                float b0 = __ldg(&bias[col]), b1 = __ldg(&bias[col + 1]);
                d[0] += b0; d[1] += b1; d[2] += b0; d[3] += b1;
            }
            if (EPI == 1) {
                float2 r0 = *reinterpret_cast<const float2*>(&resid[(size_t)row * N + col]);
                float2 r1 = *reinterpret_cast<const float2*>(&resid[(size_t)(row + 8) * N + col]);
                d[0] += r0.x; d[1] += r0.y; d[2] += r1.x; d[3] += r1.y;
                *reinterpret_cast<float2*>(&C[(size_t)row * N + col])       = make_float2(d[0], d[1]);
                *reinterpret_cast<float2*>(&C[(size_t)(row + 8) * N + col]) = make_float2(d[2], d[3]);
            } else {
                if (EPI == 2) {
                    d[0] = gelu_exact(d[0]); d[1] = gelu_exact(d[1]);
                    d[2] = gelu_exact(d[2]); d[3] = gelu_exact(d[3]);
                }
                *reinterpret_cast<__half2*>(&Ch[(size_t)row * N + col]) =
                    __half2(__float2half(d[0]), __float2half(d[1]));
                *reinterpret_cast<__half2*>(&Ch[(size_t)(row + 8) * N + col]) =
                    __half2(__float2half(d[2]), __float2half(d[3]));
            }
        }
    }
}

// ---------------- tensor-core causal flash attention (fp16, 1-pass) ----------------
#define ATT_SMEM (8192 + 2 * 16384)   // 40960

__global__ __launch_bounds__(128, 4)
void attn_mma(const __half* __restrict__ QKV,
              __half* __restrict__ O)
{
    extern __shared__ char sm[];
    uint32_t sb = smem_u32(sm);
    int tid = threadIdx.x, lane = tid & 31, w = tid >> 5;
    int bh = blockIdx.y, b = bh >> 4, h = bh & 15;
    int qt = blockIdx.x;
    const int QS = QKV_N;   // 3072

    // ---- issue Q loads ----
    {
        size_t q0 = (size_t)(b * SEQ + qt * 64) * QS + h * DK;
        #pragma unroll
        for (int i = 0; i < 4; i++) {
            int idx = tid + (i << 7);
            int r = idx >> 3, c = idx & 7;
            uint32_t so = SMEM_SWZ128((uint32_t)(r * 128 + c * 16));
            CP_ASYNC16(sb + so, (const void*)(QKV + q0 + (size_t)r * QS + c * 8));
        }
    }

    auto load_kv = [&](int kt) {
        uint32_t base = sb + 8192 + (kt & 1) * 16384;
        size_t k0 = (size_t)(b * SEQ + kt * 64) * QS + h * DK + DMODEL;
        size_t v0 = k0 + DMODEL;
        #pragma unroll
        for (int i = 0; i < 4; i++) {
            int idx = tid + (i << 7);
            int r = idx >> 3, c = idx & 7;
            uint32_t so = SMEM_SWZ128((uint32_t)(r * 128 + c * 16));
            CP_ASYNC16(base + so,        (const void*)(QKV + k0 + (size_t)r * QS + c * 8));
            CP_ASYNC16(base + 8192 + so, (const void*)(QKV + v0 + (size_t)r * QS + c * 8));
        }
        CP_COMMIT();
    };

    load_kv(0);
    CP_WAIT(0);
    __syncthreads();

    // ---- hoist Q fragments ----
    uint32_t qh[4][4];
    {
        int arow = w * 16 + (lane & 15);
        #pragma unroll
        for (int s = 0; s < 4; s++) {
            uint32_t off = SMEM_SWZ128((uint32_t)(arow * 128 + (s * 16 + ((lane >> 4) << 3)) * 2));
            ldsm_x4(qh[s], sb + off);
        }
    }

    float oacc[8][4];
    #pragma unroll
    for (int i = 0; i < 8; i++)
        #pragma unroll
        for (int e = 0; e < 4; e++) oacc[i][e] = 0.f;
    float m0 = -1e30f, m1 = -1e30f, l0 = 0.f, l1 = 0.f;

    int r0g = qt * 64 + w * 16 + (lane >> 2);
    int r1g = r0g + 8;

    for (int kt = 0; kt <= qt; kt++) {
        if (kt > 0) { CP_WAIT(0); __syncthreads(); }
        if (kt < qt) load_kv(kt + 1);

        uint32_t kbase = sb + 8192 + (kt & 1) * 16384;
        uint32_t vbase = kbase + 8192;

        // ---- S = Q K^T ----
        float sacc[8][4];
        #pragma unroll
        for (int i = 0; i < 8; i++)
            #pragma unroll
            for (int e = 0; e < 4; e++) sacc[i][e] = 0.f;

        int b_r = ((lane >> 4) << 3) + (lane & 7);
        #pragma unroll
        for (int s = 0; s < 4; s++) {
            int b_c2 = (s * 16 + (((lane >> 3) & 1) << 3)) * 2;
            #pragma unroll
            for (int np = 0; np < 4; np++) {
                uint32_t off = SMEM_SWZ128((uint32_t)((np * 16 + b_r) * 128 + b_c2));
                uint32_t th[4];
                ldsm_x4(th, kbase + off);
                uint32_t kh0[2] = {th[0], th[1]}, kh1[2] = {th[2], th[3]};
                mma16816(sacc[2*np],   qh[s], kh0);
                mma16816(sacc[2*np+1], qh[s], kh1);
            }
        }

        // ---- scale + causal mask ----
        #pragma unroll
        for (int nt = 0; nt < 8; nt++)
            #pragma unroll
            for (int e = 0; e < 4; e++) sacc[nt][e] *= 0.125f;
        if (kt == qt) {
            #pragma unroll
            for (int nt = 0; nt < 8; nt++) {
                int colb = kt * 64 + nt * 8 + 2 * (lane & 3);
                #pragma unroll
                for (int e = 0; e < 2; e++) {
                    if (colb + e > r0g) sacc[nt][e]     = -1e30f;
                    if (colb + e > r1g) sacc[nt][2 + e] = -1e30f;
                }
            }
        }

        // ---- online softmax ----
        float mx0 = sacc[0][0], mx1 = sacc[0][2];
        #pragma unroll
        for (int nt = 0; nt < 8; nt++) {
            mx0 = fmaxf(mx0, fmaxf(sacc[nt][0], sacc[nt][1]));
            mx1 = fmaxf(mx1, fmaxf(sacc[nt][2], sacc[nt][3]));
        }
        mx0 = fmaxf(mx0, __shfl_xor_sync(0xffffffffu, mx0, 1));
        mx0 = fmaxf(mx0, __shfl_xor_sync(0xffffffffu, mx0, 2));
        mx1 = fmaxf(mx1, __shfl_xor_sync(0xffffffffu, mx1, 1));
        mx1 = fmaxf(mx1, __shfl_xor_sync(0xffffffffu, mx1, 2));
        float mn0 = fmaxf(m0, mx0), mn1 = fmaxf(m1, mx1);
        float a0 = __expf(m0 - mn0), a1 = __expf(m1 - mn1);

        float sum0 = 0.f, sum1 = 0.f;
        #pragma unroll
        for (int nt = 0; nt < 8; nt++) {
            sacc[nt][0] = __expf(sacc[nt][0] - mn0);
            sacc[nt][1] = __expf(sacc[nt][1] - mn0);
            sacc[nt][2] = __expf(sacc[nt][2] - mn1);
            sacc[nt][3] = __expf(sacc[nt][3] - mn1);
            sum0 += sacc[nt][0] + sacc[nt][1];
            sum1 += sacc[nt][2] + sacc[nt][3];
        }
        sum0 += __shfl_xor_sync(0xffffffffu, sum0, 1);
        sum0 += __shfl_xor_sync(0xffffffffu, sum0, 2);
        sum1 += __shfl_xor_sync(0xffffffffu, sum1, 1);
        sum1 += __shfl_xor_sync(0xffffffffu, sum1, 2);
        l0 = l0 * a0 + sum0;  m0 = mn0;
        l1 = l1 * a1 + sum1;  m1 = mn1;
        #pragma unroll
        for (int nt = 0; nt < 8; nt++) {
            oacc[nt][0] *= a0; oacc[nt][1] *= a0;
            oacc[nt][2] *= a1; oacc[nt][3] *= a1;
        }

        // ---- O += P V ----
        int r_in = lane & 7, sel = lane >> 3;
        #pragma unroll
        for (int s = 0; s < 4; s++) {
            uint32_t pah[4];
            #pragma unroll
            for (int half = 0; half < 2; half++) {
                float* pv = sacc[2*s + half];
                pah[half*2]   = pack2h(__float2half(pv[0]), __float2half(pv[1]));
                pah[half*2+1] = pack2h(__float2half(pv[2]), __float2half(pv[3]));
            }
            int vrow = s * 16 + (sel & 1) * 8 + r_in;
            #pragma unroll
            for (int np = 0; np < 4; np++) {
                int cb = np * 32 + (sel >> 1) * 16;
                uint32_t off = SMEM_SWZ128((uint32_t)(vrow * 128 + cb));
                uint32_t vh[4];
                ldsm_x4_t(vh, vbase + off);
                uint32_t vh0[2] = {vh[0], vh[1]}, vh1[2] = {vh[2], vh[3]};
                mma16816(oacc[2*np],   pah, vh0);
                mma16816(oacc[2*np+1], pah, vh1);
            }
        }
    }

    // ---- epilogue: O /= l, write fp16 ----
    float inv0 = 1.0f / l0, inv1 = 1.0f / l1;
    int grow = b * SEQ + r0g;
    #pragma unroll
    for (int nt = 0; nt < 8; nt++) {
        int col = h * DK + nt * 8 + 2 * (lane & 3);
        *reinterpret_cast<__half2*>(&O[(size_t)grow * DMODEL + col]) =
            __half2(__float2half(oacc[nt][0] * inv0), __float2half(oacc[nt][1] * inv0));
        *reinterpret_cast<__half2*>(&O[(size_t)(grow + 8) * DMODEL + col]) =
            __half2(__float2half(oacc[nt][2] * inv1), __float2half(oacc[nt][3] * inv1));
    }
}

// ---------------- launch ----------------
extern "C" void kernel_launch(void* const* d_in, const int* in_sizes, int n_in,
                              void* d_out, int out_size)
{
    const float* x     = (const float*)d_in[0];
    const float* ln1_g = (const float*)d_in[1];
    const float* ln1_b = (const float*)d_in[2];
    const float* w_q   = (const float*)d_in[3];
    const float* w_k   = (const float*)d_in[4];
    const float* w_v   = (const float*)d_in[5];
    const float* w_o   = (const float*)d_in[6];
    const float* b_o   = (const float*)d_in[7];
    const float* ln2_g = (const float*)d_in[8];
    const float* ln2_b = (const float*)d_in[9];
    const float* w1    = (const float*)d_in[10];
    const float* b1    = (const float*)d_in[11];
    const float* w2    = (const float*)d_in[12];
    const float* b2    = (const float*)d_in[13];
    float* out = (float*)d_out;

    __half *h,*qkv,*att,*ffn,*wqkv,*wo,*w1t,*w2t;
    float *x1;
    cudaGetSymbolAddress((void**)&h,    g_h);
    cudaGetSymbolAddress((void**)&qkv,  g_qkv);
    cudaGetSymbolAddress((void**)&att,  g_att);
    cudaGetSymbolAddress((void**)&x1,   g_x1);
    cudaGetSymbolAddress((void**)&ffn,  g_ffn);
    cudaGetSymbolAddress((void**)&wqkv, g_wqkvT);
    cudaGetSymbolAddress((void**)&wo,   g_woT);
    cudaGetSymbolAddress((void**)&w1t,  g_w1T);
    cudaGetSymbolAddress((void**)&w2t,  g_w2T);

    cudaFuncSetAttribute(attn_mma, cudaFuncAttributeMaxDynamicSharedMemorySize, ATT_SMEM);
    cudaFuncSetAttribute(mma_gemm<0>, cudaFuncAttributeMaxDynamicSharedMemorySize, MG_SMEM);
    cudaFuncSetAttribute(mma_gemm<1>, cudaFuncAttributeMaxDynamicSharedMemorySize, MG_SMEM);
    cudaFuncSetAttribute(mma_gemm<2>, cudaFuncAttributeMaxDynamicSharedMemorySize, MG_SMEM);

    dim3 tb(32, 8);
    dim3 gP(DMODEL / 128, ROWS / 128);    // (8, 64)
    dim3 gF1(FFN_DIM / 128, ROWS / 128);  // (32, 64)

    // ---- Launch 1: QKV weight transpose+quantize ----
    {
        WArgs a;
        a.W[0] = w_q; a.T[0] = wqkv;
        a.W[1] = w_k; a.T[1] = wqkv + DMODEL*DMODEL;
        a.W[2] = w_v; a.T[2] = wqkv + 2*DMODEL*DMODEL;
        for (int i = 0; i < 3; i++) { a.K[i] = DMODEL; a.N[i] = DMODEL; a.tiles[i] = 1024; }
        wsplit_all<<<3072, tb>>>(a);
    }
    // ---- Launch 2: LN1 ----
    ln_kernel<<<ROWS, 256>>>(x, ln1_g, ln1_b, h);
    // ---- Launch 3: remaining weight transposes ----
    {
        WArgs a;
        a.W[0] = w_o; a.T[0] = wo;  a.K[0] = DMODEL;  a.N[0] = DMODEL;  a.tiles[0] = 1024;
        a.W[1] = w1;  a.T[1] = w1t; a.K[1] = DMODEL;  a.N[1] = FFN_DIM; a.tiles[1] = 4096;
        a.W[2] = w2;  a.T[2] = w2t; a.K[2] = FFN_DIM; a.N[2] = DMODEL;  a.tiles[2] = 4096;
        wsplit_all<<<9216, tb>>>(a);
    }
    // ---- Launch 4 (profiled): fused QKV projection -> fp16 ----
    mma_gemm<0><<<dim3(QKV_N/128, ROWS/128), 128, MG_SMEM>>>(h, wqkv,
        nullptr, nullptr, nullptr, qkv, ROWS, QKV_N, DMODEL);
    // ---- Launch 5: tensor-core attention -> fp16 ----
    attn_mma<<<dim3(SEQ / 64, BATCH * NHEAD), 128, ATT_SMEM>>>(qkv, att);
    // ---- Launch 6: O projection + bias + residual -> x1 (fp32) ----
    mma_gemm<1><<<gP, 128, MG_SMEM>>>(att, wo, b_o, x, x1, nullptr, ROWS, DMODEL, DMODEL);
    // ---- Launch 7: LN2 ----
    ln_kernel<<<ROWS, 256>>>(x1, ln2_g, ln2_b, h);
    // ---- Launch 8: FFN up + GELU -> fp16 ----
    mma_gemm<2><<<gF1, 128, MG_SMEM>>>(h, w1t, b1, nullptr, nullptr, ffn, ROWS, FFN_DIM, DMODEL);
    // ---- Launch 9: FFN down + bias + residual -> out ----
    mma_gemm<1><<<gP, 128, MG_SMEM>>>(ffn, w2t, b2, x1, out, nullptr, ROWS, DMODEL, FFN_DIM);
}

// round 13
// speedup vs baseline: 1.0964x; 1.0964x over previous
#include <cuda_runtime.h>
#include <cuda_fp16.h>
#include <math.h>
#include <stdint.h>

#define BATCH   16
#define SEQ     512
#define DMODEL  1024
#define NHEAD   16
#define DK      64
#define FFN_DIM 4096
#define ROWS    (BATCH * SEQ)        // 8192
#define QKV_N   (3 * DMODEL)         // 3072

// ---------------- scratch (device globals; no allocation) ----------------
__device__ __half g_h   [ROWS * DMODEL];
__device__ __half g_qkv [ROWS * QKV_N];
__device__ __half g_att [ROWS * DMODEL];
__device__ float  g_x1  [ROWS * DMODEL];
__device__ __half g_ffn [ROWS * FFN_DIM];
// transposed fp16 weights: T[N,K]
__device__ __half g_wqkvT[QKV_N*DMODEL];
__device__ __half g_woT  [DMODEL*DMODEL];
__device__ __half g_w1T  [DMODEL*FFN_DIM];
__device__ __half g_w2T  [FFN_DIM*DMODEL];

// ---------------- helpers ----------------
__device__ __forceinline__ uint32_t smem_u32(const void* p) {
    uint32_t a;
    asm("{ .reg .u64 t; cvta.to.shared.u64 t, %1; cvt.u32.u64 %0, t; }" : "=r"(a) : "l"(p));
    return a;
}
#define CP_ASYNC16(dst, src) \
    asm volatile("cp.async.cg.shared.global [%0], [%1], 16;" :: "r"(dst), "l"(src) : "memory")
#define CP_COMMIT() asm volatile("cp.async.commit_group;" ::: "memory")
#define CP_WAIT(n)  asm volatile("cp.async.wait_group %0;" :: "n"(n) : "memory")
#define SMEM_SWZ128(off) ((off) ^ (((off) >> 3) & 0x70))
#define SMEM_SWZ64(off)  ((off) ^ (((off) >> 3) & 0x30))

__device__ __forceinline__ void ldsm_x4(uint32_t* r, uint32_t addr) {
    asm volatile("ldmatrix.sync.aligned.m8n8.x4.shared.b16 {%0,%1,%2,%3}, [%4];"
        : "=r"(r[0]), "=r"(r[1]), "=r"(r[2]), "=r"(r[3]) : "r"(addr));
}
__device__ __forceinline__ void ldsm_x4_t(uint32_t* r, uint32_t addr) {
    asm volatile("ldmatrix.sync.aligned.m8n8.x4.trans.shared.b16 {%0,%1,%2,%3}, [%4];"
        : "=r"(r[0]), "=r"(r[1]), "=r"(r[2]), "=r"(r[3]) : "r"(addr));
}
__device__ __forceinline__ void mma16816(float* d, const uint32_t* a, const uint32_t* b) {
    asm volatile("mma.sync.aligned.m16n8k16.row.col.f32.f16.f16.f32 "
        "{%0,%1,%2,%3}, {%4,%5,%6,%7}, {%8,%9}, {%0,%1,%2,%3};"
        : "+f"(d[0]), "+f"(d[1]), "+f"(d[2]), "+f"(d[3])
        : "r"(a[0]), "r"(a[1]), "r"(a[2]), "r"(a[3]), "r"(b[0]), "r"(b[1]));
}

__device__ __forceinline__ float gelu_exact(float v) {
    return 0.5f * v * (1.0f + erff(v * 0.70710678118654752f));
}
__device__ __forceinline__ uint32_t pack2h(__half a, __half b) {
    __half2 t(a, b);
    return *reinterpret_cast<uint32_t*>(&t);
}

// ---------------- fused weight transpose + fp16 quantize (ALL weights, 1 launch) ----------------
struct WArgs {
    const float* W[6];
    __half*      T[6];
    int K[6], N[6];
    int cum[6];     // cumulative tile counts
};

__global__ void wsplit_all(WArgs a)
{
    __shared__ float t[32][33];
    int idx = blockIdx.x;
    int m = 0;
    #pragma unroll
    for (int i = 0; i < 5; i++) m += (idx >= a.cum[i]);
    if (m > 0) idx -= a.cum[m - 1];
    const float* W = a.W[m];
    __half* T = a.T[m];
    int K = a.K[m], N = a.N[m];
    int ntx = N >> 5;
    int n0 = (idx % ntx) * 32, k0 = (idx / ntx) * 32;

    int tx = threadIdx.x, ty = threadIdx.y;
    #pragma unroll
    for (int i = 0; i < 4; i++)
        t[ty + 8*i][tx] = W[(size_t)(k0 + ty + 8*i) * N + n0 + tx];
    __syncthreads();
    #pragma unroll
    for (int i = 0; i < 4; i++) {
        size_t o = (size_t)(n0 + ty + 8*i) * K + k0 + tx;
        T[o] = __float2half(t[tx][ty + 8*i]);
    }
}

// ---------------- LayerNorm: 2 rows per block (one per 128-thread group) ----------------
__global__ void ln_kernel(const float* __restrict__ x,
                          const float* __restrict__ g,
                          const float* __restrict__ b,
                          __half* __restrict__ oh)
{
    int grp = threadIdx.x >> 7;            // 0..1
    int t   = threadIdx.x & 127;           // 0..127, handles 2 float4 each
    int row = blockIdx.x * 2 + grp;

    const float4* xr = reinterpret_cast<const float4*>(x + (size_t)row * DMODEL);
    float4 v0 = xr[t], v1 = xr[t + 128];
    float s  = v0.x + v0.y + v0.z + v0.w + v1.x + v1.y + v1.z + v1.w;
    float sq = v0.x*v0.x + v0.y*v0.y + v0.z*v0.z + v0.w*v0.w
             + v1.x*v1.x + v1.y*v1.y + v1.z*v1.z + v1.w*v1.w;

    __shared__ float red_s[2][4], red_q[2][4];
    for (int o = 16; o > 0; o >>= 1) {
        s  += __shfl_xor_sync(0xffffffffu, s,  o);
        sq += __shfl_xor_sync(0xffffffffu, sq, o);
    }
    int wid = t >> 5, lid = t & 31;
    if (lid == 0) { red_s[grp][wid] = s; red_q[grp][wid] = sq; }
    __syncthreads();
    float ss = red_s[grp][0] + red_s[grp][1] + red_s[grp][2] + red_s[grp][3];
    float qq = red_q[grp][0] + red_q[grp][1] + red_q[grp][2] + red_q[grp][3];

    float mean = ss * (1.0f / DMODEL);
    float var  = qq * (1.0f / DMODEL) - mean * mean;
    float rstd = rsqrtf(var + 1e-5f);

    float4 gv0 = reinterpret_cast<const float4*>(g)[t];
    float4 bv0 = reinterpret_cast<const float4*>(b)[t];
    float4 gv1 = reinterpret_cast<const float4*>(g)[t + 128];
    float4 bv1 = reinterpret_cast<const float4*>(b)[t + 128];
    float o0 = (v0.x - mean) * rstd * gv0.x + bv0.x;
    float o1 = (v0.y - mean) * rstd * gv0.y + bv0.y;
    float o2 = (v0.z - mean) * rstd * gv0.z + bv0.z;
    float o3 = (v0.w - mean) * rstd * gv0.w + bv0.w;
    float o4 = (v1.x - mean) * rstd * gv1.x + bv1.x;
    float o5 = (v1.y - mean) * rstd * gv1.y + bv1.y;
    float o6 = (v1.z - mean) * rstd * gv1.z + bv1.z;
    float o7 = (v1.w - mean) * rstd * gv1.w + bv1.w;
    __half2* ph = reinterpret_cast<__half2*>(oh + (size_t)row * DMODEL);
    ph[t*2]       = __half2(__float2half(o0), __float2half(o1));
    ph[t*2+1]     = __half2(__float2half(o2), __float2half(o3));
    ph[256 + t*2]   = __half2(__float2half(o4), __float2half(o5));
    ph[256 + t*2+1] = __half2(__float2half(o6), __float2half(o7));
}

// ---------------- CUTLASS-shape fp16 GEMM (R11, best measured) ----------------
// CTA 128x128, 4 warps (2M x 2N), warp tile 64x64, KBLK=32, 5 stages, 2 CTAs/SM.
// Cross-barrier register pipeline: the stage-(kb+1) wait+sync sits between
// kk0 and kk1; kk1's MMAs run from registers while next kk0 frags load.
// EPI: 0 = fp16 C; 1 = +bias +resid -> fp32 C; 2 = +bias, GELU -> fp16 C
#define KBLK 32
#define A_ST_BYTES 8192              // 128 rows x 64B
#define STAGE_BYTES 16384            // A 8K | B 8K
#define NSTAGE 5
#define MG_SMEM (NSTAGE * STAGE_BYTES)   // 81920

template<int EPI>
__global__ __launch_bounds__(128, 2)
void mma_gemm(const __half* __restrict__ A, const __half* __restrict__ B,
              const float* __restrict__ bias, const float* __restrict__ resid,
              float* __restrict__ C, __half* __restrict__ Ch,
              int M, int N, int K)
{
    extern __shared__ char sm[];
    uint32_t sb = smem_u32(sm);

    int tid  = threadIdx.x;
    int wid  = tid >> 5;
    int lane = tid & 31;
    int wm   = wid & 1;          // 0..1 (M)
    int wn   = wid >> 1;         // 0..1 (N)

    int row0 = blockIdx.y * 128, col0 = blockIdx.x * 128;
    const __half* pA = A + (size_t)row0 * K;
    const __half* pB = B + (size_t)col0 * K;

    int KB = K / KBLK;

    // cp.async: per tensor 128 rows x 4 chunks(16B); 4 chunks/thread
    int ld_r[4], ld_c[4];
    uint32_t ld_so[4];
    #pragma unroll
    for (int i = 0; i < 4; i++) {
        int idx = tid + (i << 7);
        ld_r[i] = idx >> 2;
        ld_c[i] = idx & 3;
        ld_so[i] = SMEM_SWZ64((uint32_t)(ld_r[i] * 64 + ld_c[i] * 16));
    }

    auto stage_base = [&](int kb) {
        return sb + (uint32_t)(kb % NSTAGE) * STAGE_BYTES;
    };

    auto load_stage = [&](int kb) {
        uint32_t base = stage_base(kb);
        int koff = kb * KBLK;
        #pragma unroll
        for (int i = 0; i < 4; i++) {
            size_t go = (size_t)ld_r[i] * K + koff + ld_c[i] * 8;
            CP_ASYNC16(base + ld_so[i],              (const void*)(pA + go));
            CP_ASYNC16(base + A_ST_BYTES + ld_so[i], (const void*)(pB + go));
        }
        CP_COMMIT();
    };

    // fragment load: A m64k16 (4 x4) + B n64k16 (4 x4) for one kk
    int a_lane_row = lane & 15;
    int a_lane_c   = (lane >> 4) << 4;        // byte offset within k16 (0 or 16)
    int b_lane_row = ((lane >> 4) << 3) + (lane & 7);
    int b_lane_c   = ((lane >> 3) & 1) << 4;
    auto ld_frags = [&](uint32_t base, int kk,
                        uint32_t (*ahb)[4], uint32_t (*bhb)[2]) {
        uint32_t sA = base, sB = base + A_ST_BYTES;
        int acol = kk * 32 + a_lane_c;
        #pragma unroll
        for (int mt = 0; mt < 4; mt++) {
            int row = wm * 64 + mt * 16 + a_lane_row;
            uint32_t off = SMEM_SWZ64((uint32_t)(row * 64 + acol));
            ldsm_x4(ahb[mt], sA + off);
        }
        int bcol = kk * 32 + b_lane_c;
        #pragma unroll
        for (int p = 0; p < 4; p++) {
            int brow = wn * 64 + p * 16 + b_lane_row;
            uint32_t off = SMEM_SWZ64((uint32_t)(brow * 64 + bcol));
            uint32_t t[4];
            ldsm_x4(t, sB + off);
            bhb[p*2][0] = t[0]; bhb[p*2][1] = t[1];
            bhb[p*2+1][0] = t[2]; bhb[p*2+1][1] = t[3];
        }
    };

    float acc[4][8][4];
    #pragma unroll
    for (int i = 0; i < 4; i++)
        #pragma unroll
        for (int j = 0; j < 8; j++)
            #pragma unroll
            for (int e = 0; e < 4; e++) acc[i][j][e] = 0.f;

    // prologue: fill NSTAGE-1 stages
    #pragma unroll
    for (int s = 0; s < NSTAGE - 1; s++) load_stage(s);
    CP_WAIT(NSTAGE - 2);      // stage 0 landed
    __syncthreads();

    uint32_t ah[2][4][4], bh[2][8][2];
    ld_frags(stage_base(0), 0, ah[0], bh[0]);

    for (int kb = 0; kb < KB; kb++) {
        #pragma unroll
        for (int kk = 0; kk < 2; kk++) {
            int cur = (kb * 2 + kk) & 1;
            int nxt = cur ^ 1;
            if (kk == 1) {
                // issue future stage, then sync for stage kb+1, then load its kk0
                if (kb + NSTAGE - 1 < KB) load_stage(kb + NSTAGE - 1);
                else                      CP_COMMIT();
                CP_WAIT(NSTAGE - 2);
                __syncthreads();
                if (kb + 1 < KB)
                    ld_frags(stage_base(kb + 1), 0, ah[nxt], bh[nxt]);
            } else {
                ld_frags(stage_base(kb), 1, ah[nxt], bh[nxt]);
            }
            #pragma unroll
            for (int mt = 0; mt < 4; mt++)
                #pragma unroll
                for (int nt = 0; nt < 8; nt++)
                    mma16816(acc[mt][nt], ah[cur][mt], bh[cur][nt]);
        }
    }

    // epilogue
    int g  = lane >> 2;
    int c2 = (lane & 3) * 2;
    #pragma unroll
    for (int mt = 0; mt < 4; mt++) {
        #pragma unroll
        for (int nt = 0; nt < 8; nt++) {
            int row = row0 + wm * 64 + mt * 16 + g;
            int col = col0 + wn * 64 + nt * 8 + c2;
            float d[4] = {acc[mt][nt][0], acc[mt][nt][1], acc[mt][nt][2], acc[mt][nt][3]};
            if (EPI >= 1) {
                float b0 = __ldg(&bias[col]), b1 = __ldg(&bias[col + 1]);
                d[0] += b0; d[1] += b1; d[2] += b0; d[3] += b1;
            }
            if (EPI == 1) {
                float2 r0 = *reinterpret_cast<const float2*>(&resid[(size_t)row * N + col]);
                float2 r1 = *reinterpret_cast<const float2*>(&resid[(size_t)(row + 8) * N + col]);
                d[0] += r0.x; d[1] += r0.y; d[2] += r1.x; d[3] += r1.y;
                *reinterpret_cast<float2*>(&C[(size_t)row * N + col])       = make_float2(d[0], d[1]);
                *reinterpret_cast<float2*>(&C[(size_t)(row + 8) * N + col]) = make_float2(d[2], d[3]);
            } else {
                if (EPI == 2) {
                    d[0] = gelu_exact(d[0]); d[1] = gelu_exact(d[1]);
                    d[2] = gelu_exact(d[2]); d[3] = gelu_exact(d[3]);
                }
                *reinterpret_cast<__half2*>(&Ch[(size_t)row * N + col]) =
                    __half2(__float2half(d[0]), __float2half(d[1]));
                *reinterpret_cast<__half2*>(&Ch[(size_t)(row + 8) * N + col]) =
                    __half2(__float2half(d[2]), __float2half(d[3]));
            }
        }
    }
}

// ---------------- tensor-core causal flash attention (fp16, 1-pass) ----------------
#define ATT_SMEM (8192 + 2 * 16384)   // 40960

__global__ __launch_bounds__(128, 4)
void attn_mma(const __half* __restrict__ QKV,
              __half* __restrict__ O)
{
    extern __shared__ char sm[];
    uint32_t sb = smem_u32(sm);
    int tid = threadIdx.x, lane = tid & 31, w = tid >> 5;
    int bh = blockIdx.y, b = bh >> 4, h = bh & 15;
    int qt = blockIdx.x;
    const int QS = QKV_N;   // 3072

    // ---- issue Q loads ----
    {
        size_t q0 = (size_t)(b * SEQ + qt * 64) * QS + h * DK;
        #pragma unroll
        for (int i = 0; i < 4; i++) {
            int idx = tid + (i << 7);
            int r = idx >> 3, c = idx & 7;
            uint32_t so = SMEM_SWZ128((uint32_t)(r * 128 + c * 16));
            CP_ASYNC16(sb + so, (const void*)(QKV + q0 + (size_t)r * QS + c * 8));
        }
    }

    auto load_kv = [&](int kt) {
        uint32_t base = sb + 8192 + (kt & 1) * 16384;
        size_t k0 = (size_t)(b * SEQ + kt * 64) * QS + h * DK + DMODEL;
        size_t v0 = k0 + DMODEL;
        #pragma unroll
        for (int i = 0; i < 4; i++) {
            int idx = tid + (i << 7);
            int r = idx >> 3, c = idx & 7;
            uint32_t so = SMEM_SWZ128((uint32_t)(r * 128 + c * 16));
            CP_ASYNC16(base + so,        (const void*)(QKV + k0 + (size_t)r * QS + c * 8));
            CP_ASYNC16(base + 8192 + so, (const void*)(QKV + v0 + (size_t)r * QS + c * 8));
        }
        CP_COMMIT();
    };

    load_kv(0);
    CP_WAIT(0);
    __syncthreads();

    // ---- hoist Q fragments ----
    uint32_t qh[4][4];
    {
        int arow = w * 16 + (lane & 15);
        #pragma unroll
        for (int s = 0; s < 4; s++) {
            uint32_t off = SMEM_SWZ128((uint32_t)(arow * 128 + (s * 16 + ((lane >> 4) << 3)) * 2));
            ldsm_x4(qh[s], sb + off);
        }
    }

    float oacc[8][4];
    #pragma unroll
    for (int i = 0; i < 8; i++)
        #pragma unroll
        for (int e = 0; e < 4; e++) oacc[i][e] = 0.f;
    float m0 = -1e30f, m1 = -1e30f, l0 = 0.f, l1 = 0.f;

    int r0g = qt * 64 + w * 16 + (lane >> 2);
    int r1g = r0g + 8;

    for (int kt = 0; kt <= qt; kt++) {
        if (kt > 0) { CP_WAIT(0); __syncthreads(); }
        if (kt < qt) load_kv(kt + 1);

        uint32_t kbase = sb + 8192 + (kt & 1) * 16384;
        uint32_t vbase = kbase + 8192;

        // ---- S = Q K^T ----
        float sacc[8][4];
        #pragma unroll
        for (int i = 0; i < 8; i++)
            #pragma unroll
            for (int e = 0; e < 4; e++) sacc[i][e] = 0.f;

        int b_r = ((lane >> 4) << 3) + (lane & 7);
        #pragma unroll
        for (int s = 0; s < 4; s++) {
            int b_c2 = (s * 16 + (((lane >> 3) & 1) << 3)) * 2;
            #pragma unroll
            for (int np = 0; np < 4; np++) {
                uint32_t off = SMEM_SWZ128((uint32_t)((np * 16 + b_r) * 128 + b_c2));
                uint32_t th[4];
                ldsm_x4(th, kbase + off);
                uint32_t kh0[2] = {th[0], th[1]}, kh1[2] = {th[2], th[3]};
                mma16816(sacc[2*np],   qh[s], kh0);
                mma16816(sacc[2*np+1], qh[s], kh1);
            }
        }

        // ---- scale + causal mask ----
        #pragma unroll
        for (int nt = 0; nt < 8; nt++)
            #pragma unroll
            for (int e = 0; e < 4; e++) sacc[nt][e] *= 0.125f;
        if (kt == qt) {
            #pragma unroll
            for (int nt = 0; nt < 8; nt++) {
                int colb = kt * 64 + nt * 8 + 2 * (lane & 3);
                #pragma unroll
                for (int e = 0; e < 2; e++) {
                    if (colb + e > r0g) sacc[nt][e]     = -1e30f;
                    if (colb + e > r1g) sacc[nt][2 + e] = -1e30f;
                }
            }
        }

        // ---- online softmax ----
        float mx0 = sacc[0][0], mx1 = sacc[0][2];
        #pragma unroll
        for (int nt = 0; nt < 8; nt++) {
            mx0 = fmaxf(mx0, fmaxf(sacc[nt][0], sacc[nt][1]));
            mx1 = fmaxf(mx1, fmaxf(sacc[nt][2], sacc[nt][3]));
        }
        mx0 = fmaxf(mx0, __shfl_xor_sync(0xffffffffu, mx0, 1));
        mx0 = fmaxf(mx0, __shfl_xor_sync(0xffffffffu, mx0, 2));
        mx1 = fmaxf(mx1, __shfl_xor_sync(0xffffffffu, mx1, 1));
        mx1 = fmaxf(mx1, __shfl_xor_sync(0xffffffffu, mx1, 2));
        float mn0 = fmaxf(m0, mx0), mn1 = fmaxf(m1, mx1);
        float a0 = __expf(m0 - mn0), a1 = __expf(m1 - mn1);

        float sum0 = 0.f, sum1 = 0.f;
        #pragma unroll
        for (int nt = 0; nt < 8; nt++) {
            sacc[nt][0] = __expf(sacc[nt][0] - mn0);
            sacc[nt][1] = __expf(sacc[nt][1] - mn0);
            sacc[nt][2] = __expf(sacc[nt][2] - mn1);
            sacc[nt][3] = __expf(sacc[nt][3] - mn1);
            sum0 += sacc[nt][0] + sacc[nt][1];
            sum1 += sacc[nt][2] + sacc[nt][3];
        }
        sum0 += __shfl_xor_sync(0xffffffffu, sum0, 1);
        sum0 += __shfl_xor_sync(0xffffffffu, sum0, 2);
        sum1 += __shfl_xor_sync(0xffffffffu, sum1, 1);
        sum1 += __shfl_xor_sync(0xffffffffu, sum1, 2);
        l0 = l0 * a0 + sum0;  m0 = mn0;
        l1 = l1 * a1 + sum1;  m1 = mn1;
        #pragma unroll
        for (int nt = 0; nt < 8; nt++) {
            oacc[nt][0] *= a0; oacc[nt][1] *= a0;
            oacc[nt][2] *= a1; oacc[nt][3] *= a1;
        }

        // ---- O += P V ----
        int r_in = lane & 7, sel = lane >> 3;
        #pragma unroll
        for (int s = 0; s < 4; s++) {
            uint32_t pah[4];
            #pragma unroll
            for (int half = 0; half < 2; half++) {
                float* pv = sacc[2*s + half];
                pah[half*2]   = pack2h(__float2half(pv[0]), __float2half(pv[1]));
                pah[half*2+1] = pack2h(__float2half(pv[2]), __float2half(pv[3]));
            }
            int vrow = s * 16 + (sel & 1) * 8 + r_in;
            #pragma unroll
            for (int np = 0; np < 4; np++) {
                int cb = np * 32 + (sel >> 1) * 16;
                uint32_t off = SMEM_SWZ128((uint32_t)(vrow * 128 + cb));
                uint32_t vh[4];
                ldsm_x4_t(vh, vbase + off);
                uint32_t vh0[2] = {vh[0], vh[1]}, vh1[2] = {vh[2], vh[3]};
                mma16816(oacc[2*np],   pah, vh0);
                mma16816(oacc[2*np+1], pah, vh1);
            }
        }
    }

    // ---- epilogue: O /= l, write fp16 ----
    float inv0 = 1.0f / l0, inv1 = 1.0f / l1;
    int grow = b * SEQ + r0g;
    #pragma unroll
    for (int nt = 0; nt < 8; nt++) {
        int col = h * DK + nt * 8 + 2 * (lane & 3);
        *reinterpret_cast<__half2*>(&O[(size_t)grow * DMODEL + col]) =
            __half2(__float2half(oacc[nt][0] * inv0), __float2half(oacc[nt][1] * inv0));
        *reinterpret_cast<__half2*>(&O[(size_t)(grow + 8) * DMODEL + col]) =
            __half2(__float2half(oacc[nt][2] * inv1), __float2half(oacc[nt][3] * inv1));
    }
}

// ---------------- launch ----------------
extern "C" void kernel_launch(void* const* d_in, const int* in_sizes, int n_in,
                              void* d_out, int out_size)
{
    const float* x     = (const float*)d_in[0];
    const float* ln1_g = (const float*)d_in[1];
    const float* ln1_b = (const float*)d_in[2];
    const float* w_q   = (const float*)d_in[3];
    const float* w_k   = (const float*)d_in[4];
    const float* w_v   = (const float*)d_in[5];
    const float* w_o   = (const float*)d_in[6];
    const float* b_o   = (const float*)d_in[7];
    const float* ln2_g = (const float*)d_in[8];
    const float* ln2_b = (const float*)d_in[9];
    const float* w1    = (const float*)d_in[10];
    const float* b1    = (const float*)d_in[11];
    const float* w2    = (const float*)d_in[12];
    const float* b2    = (const float*)d_in[13];
    float* out = (float*)d_out;

    __half *h,*qkv,*att,*ffn,*wqkv,*wo,*w1t,*w2t;
    float *x1;
    cudaGetSymbolAddress((void**)&h,    g_h);
    cudaGetSymbolAddress((void**)&qkv,  g_qkv);
    cudaGetSymbolAddress((void**)&att,  g_att);
    cudaGetSymbolAddress((void**)&x1,   g_x1);
    cudaGetSymbolAddress((void**)&ffn,  g_ffn);
    cudaGetSymbolAddress((void**)&wqkv, g_wqkvT);
    cudaGetSymbolAddress((void**)&wo,   g_woT);
    cudaGetSymbolAddress((void**)&w1t,  g_w1T);
    cudaGetSymbolAddress((void**)&w2t,  g_w2T);

    cudaFuncSetAttribute(attn_mma, cudaFuncAttributeMaxDynamicSharedMemorySize, ATT_SMEM);
    cudaFuncSetAttribute(mma_gemm<0>, cudaFuncAttributeMaxDynamicSharedMemorySize, MG_SMEM);
    cudaFuncSetAttribute(mma_gemm<1>, cudaFuncAttributeMaxDynamicSharedMemorySize, MG_SMEM);
    cudaFuncSetAttribute(mma_gemm<2>, cudaFuncAttributeMaxDynamicSharedMemorySize, MG_SMEM);

    dim3 tb(32, 8);
    dim3 gP(DMODEL / 128, ROWS / 128);    // (8, 64)
    dim3 gF1(FFN_DIM / 128, ROWS / 128);  // (32, 64)

    // ---- Launch 1: ALL weight transposes+quantize (12288 tiles) ----
    {
        WArgs a;
        a.W[0] = w_q; a.T[0] = wqkv;                   a.K[0] = DMODEL;  a.N[0] = DMODEL;
        a.W[1] = w_k; a.T[1] = wqkv + DMODEL*DMODEL;   a.K[1] = DMODEL;  a.N[1] = DMODEL;
        a.W[2] = w_v; a.T[2] = wqkv + 2*DMODEL*DMODEL; a.K[2] = DMODEL;  a.N[2] = DMODEL;
        a.W[3] = w_o; a.T[3] = wo;                     a.K[3] = DMODEL;  a.N[3] = DMODEL;
        a.W[4] = w1;  a.T[4] = w1t;                    a.K[4] = DMODEL;  a.N[4] = FFN_DIM;
        a.W[5] = w2;  a.T[5] = w2t;                    a.K[5] = FFN_DIM; a.N[5] = DMODEL;
        int tiles[6] = {1024, 1024, 1024, 1024, 4096, 4096};
        int c = 0;
        for (int i = 0; i < 6; i++) { c += tiles[i]; a.cum[i] = c; }
        wsplit_all<<<12288, tb>>>(a);
    }
    // ---- Launch 2: LN1 ----
    ln_kernel<<<ROWS / 2, 256>>>(x, ln1_g, ln1_b, h);
    // ---- Launch 3: fused QKV projection -> fp16 ----
    mma_gemm<0><<<dim3(QKV_N/128, ROWS/128), 128, MG_SMEM>>>(h, wqkv,
        nullptr, nullptr, nullptr, qkv, ROWS, QKV_N, DMODEL);
    // ---- Launch 4 (profiled): tensor-core attention -> fp16 ----
    attn_mma<<<dim3(SEQ / 64, BATCH * NHEAD), 128, ATT_SMEM>>>(qkv, att);
    // ---- Launch 5: O projection + bias + residual -> x1 (fp32) ----
    mma_gemm<1><<<gP, 128, MG_SMEM>>>(att, wo, b_o, x, x1, nullptr, ROWS, DMODEL, DMODEL);
    // ---- Launch 6: LN2 ----
    ln_kernel<<<ROWS / 2, 256>>>(x1, ln2_g, ln2_b, h);
    // ---- Launch 7: FFN up + GELU -> fp16 ----
    mma_gemm<2><<<gF1, 128, MG_SMEM>>>(h, w1t, b1, nullptr, nullptr, ffn, ROWS, FFN_DIM, DMODEL);
    // ---- Launch 8: FFN down + bias + residual -> out ----
    mma_gemm<1><<<gP, 128, MG_SMEM>>>(ffn, w2t, b2, x1, out, nullptr, ROWS, DMODEL, FFN_DIM);
}

// round 14
// speedup vs baseline: 1.0984x; 1.0018x over previous
#include <cuda_runtime.h>
#include <cuda_fp16.h>
#include <math.h>
#include <stdint.h>

#define BATCH   16
#define SEQ     512
#define DMODEL  1024
#define NHEAD   16
#define DK      64
#define FFN_DIM 4096
#define ROWS    (BATCH * SEQ)        // 8192
#define QKV_N   (3 * DMODEL)         // 3072

// ---------------- scratch (device globals; no allocation) ----------------
__device__ __half g_h   [ROWS * DMODEL];
__device__ __half g_qkv [ROWS * QKV_N];
__device__ __half g_att [ROWS * DMODEL];
__device__ float  g_x1  [ROWS * DMODEL];
__device__ __half g_ffn [ROWS * FFN_DIM];
// transposed fp16 weights: T[N,K]
__device__ __half g_wqkvT[QKV_N*DMODEL];
__device__ __half g_woT  [DMODEL*DMODEL];
__device__ __half g_w1T  [DMODEL*FFN_DIM];
__device__ __half g_w2T  [FFN_DIM*DMODEL];

// ---------------- helpers ----------------
__device__ __forceinline__ uint32_t smem_u32(const void* p) {
    uint32_t a;
    asm("{ .reg .u64 t; cvta.to.shared.u64 t, %1; cvt.u32.u64 %0, t; }" : "=r"(a) : "l"(p));
    return a;
}
#define CP_ASYNC16(dst, src) \
    asm volatile("cp.async.cg.shared.global [%0], [%1], 16;" :: "r"(dst), "l"(src) : "memory")
#define CP_COMMIT() asm volatile("cp.async.commit_group;" ::: "memory")
#define CP_WAIT(n)  asm volatile("cp.async.wait_group %0;" :: "n"(n) : "memory")
#define SMEM_SWZ128(off) ((off) ^ (((off) >> 3) & 0x70))
#define SMEM_SWZ64(off)  ((off) ^ (((off) >> 3) & 0x30))

__device__ __forceinline__ void ldsm_x4(uint32_t* r, uint32_t addr) {
    asm volatile("ldmatrix.sync.aligned.m8n8.x4.shared.b16 {%0,%1,%2,%3}, [%4];"
        : "=r"(r[0]), "=r"(r[1]), "=r"(r[2]), "=r"(r[3]) : "r"(addr));
}
__device__ __forceinline__ void ldsm_x4_t(uint32_t* r, uint32_t addr) {
    asm volatile("ldmatrix.sync.aligned.m8n8.x4.trans.shared.b16 {%0,%1,%2,%3}, [%4];"
        : "=r"(r[0]), "=r"(r[1]), "=r"(r[2]), "=r"(r[3]) : "r"(addr));
}
__device__ __forceinline__ void mma16816(float* d, const uint32_t* a, const uint32_t* b) {
    asm volatile("mma.sync.aligned.m16n8k16.row.col.f32.f16.f16.f32 "
        "{%0,%1,%2,%3}, {%4,%5,%6,%7}, {%8,%9}, {%0,%1,%2,%3};"
        : "+f"(d[0]), "+f"(d[1]), "+f"(d[2]), "+f"(d[3])
        : "r"(a[0]), "r"(a[1]), "r"(a[2]), "r"(a[3]), "r"(b[0]), "r"(b[1]));
}

__device__ __forceinline__ float gelu_exact(float v) {
    return 0.5f * v * (1.0f + erff(v * 0.70710678118654752f));
}
__device__ __forceinline__ uint32_t pack2h(__half a, __half b) {
    __half2 t(a, b);
    return *reinterpret_cast<uint32_t*>(&t);
}

// ---------------- fused weight transpose + fp16 quantize (ALL weights, 1 launch) ----------------
// 64(k) x 32(n) tiles; half2 writes along K -> full 128B write transactions.
struct WArgs {
    const float* W[6];
    __half*      T[6];
    int K[6], N[6];
    int cum[6];     // cumulative tile counts
};

__global__ void wsplit_all(WArgs a)
{
    __shared__ float t[64][33];
    int idx = blockIdx.x;
    int m = 0;
    #pragma unroll
    for (int i = 0; i < 5; i++) m += (idx >= a.cum[i]);
    if (m > 0) idx -= a.cum[m - 1];
    const float* W = a.W[m];
    __half* T = a.T[m];
    int K = a.K[m], N = a.N[m];
    int ntx = N >> 5;
    int n0 = (idx % ntx) * 32, k0 = (idx / ntx) * 64;

    int tx = threadIdx.x, ty = threadIdx.y;
    #pragma unroll
    for (int i = 0; i < 8; i++)
        t[ty + 8*i][tx] = W[(size_t)(k0 + ty + 8*i) * N + n0 + tx];
    __syncthreads();
    #pragma unroll
    for (int i = 0; i < 4; i++) {
        int ny = ty * 4 + i;
        __half2 hv(__float2half(t[tx*2][ny]), __float2half(t[tx*2 + 1][ny]));
        *reinterpret_cast<__half2*>(&T[(size_t)(n0 + ny) * K + k0 + tx*2]) = hv;
    }
}

// ---------------- LayerNorm: 2 rows per block (one per 128-thread group) ----------------
__global__ void ln_kernel(const float* __restrict__ x,
                          const float* __restrict__ g,
                          const float* __restrict__ b,
                          __half* __restrict__ oh)
{
    int grp = threadIdx.x >> 7;            // 0..1
    int t   = threadIdx.x & 127;           // 0..127, handles 2 float4 each
    int row = blockIdx.x * 2 + grp;

    const float4* xr = reinterpret_cast<const float4*>(x + (size_t)row * DMODEL);
    float4 v0 = xr[t], v1 = xr[t + 128];
    float s  = v0.x + v0.y + v0.z + v0.w + v1.x + v1.y + v1.z + v1.w;
    float sq = v0.x*v0.x + v0.y*v0.y + v0.z*v0.z + v0.w*v0.w
             + v1.x*v1.x + v1.y*v1.y + v1.z*v1.z + v1.w*v1.w;

    __shared__ float red_s[2][4], red_q[2][4];
    for (int o = 16; o > 0; o >>= 1) {
        s  += __shfl_xor_sync(0xffffffffu, s,  o);
        sq += __shfl_xor_sync(0xffffffffu, sq, o);
    }
    int wid = t >> 5, lid = t & 31;
    if (lid == 0) { red_s[grp][wid] = s; red_q[grp][wid] = sq; }
    __syncthreads();
    float ss = red_s[grp][0] + red_s[grp][1] + red_s[grp][2] + red_s[grp][3];
    float qq = red_q[grp][0] + red_q[grp][1] + red_q[grp][2] + red_q[grp][3];

    float mean = ss * (1.0f / DMODEL);
    float var  = qq * (1.0f / DMODEL) - mean * mean;
    float rstd = rsqrtf(var + 1e-5f);

    float4 gv0 = reinterpret_cast<const float4*>(g)[t];
    float4 bv0 = reinterpret_cast<const float4*>(b)[t];
    float4 gv1 = reinterpret_cast<const float4*>(g)[t + 128];
    float4 bv1 = reinterpret_cast<const float4*>(b)[t + 128];
    float o0 = (v0.x - mean) * rstd * gv0.x + bv0.x;
    float o1 = (v0.y - mean) * rstd * gv0.y + bv0.y;
    float o2 = (v0.z - mean) * rstd * gv0.z + bv0.z;
    float o3 = (v0.w - mean) * rstd * gv0.w + bv0.w;
    float o4 = (v1.x - mean) * rstd * gv1.x + bv1.x;
    float o5 = (v1.y - mean) * rstd * gv1.y + bv1.y;
    float o6 = (v1.z - mean) * rstd * gv1.z + bv1.z;
    float o7 = (v1.w - mean) * rstd * gv1.w + bv1.w;
    __half2* ph = reinterpret_cast<__half2*>(oh + (size_t)row * DMODEL);
    ph[t*2]       = __half2(__float2half(o0), __float2half(o1));
    ph[t*2+1]     = __half2(__float2half(o2), __float2half(o3));
    ph[256 + t*2]   = __half2(__float2half(o4), __float2half(o5));
    ph[256 + t*2+1] = __half2(__float2half(o6), __float2half(o7));
}

// ---------------- CUTLASS-shape fp16 GEMM (R11 mainloop, 6 stages) ----------------
// CTA 128x128, 4 warps (2M x 2N), warp tile 64x64, KBLK=32, 6 stages, 2 CTAs/SM.
// EPI: 0 = fp16 C; 1 = +bias +resid -> fp32 C; 2 = +bias, GELU -> fp16 C
#define KBLK 32
#define A_ST_BYTES 8192              // 128 rows x 64B
#define STAGE_BYTES 16384            // A 8K | B 8K
#define NSTAGE 6
#define MG_SMEM (NSTAGE * STAGE_BYTES)   // 98304

template<int EPI>
__global__ __launch_bounds__(128, 2)
void mma_gemm(const __half* __restrict__ A, const __half* __restrict__ B,
              const float* __restrict__ bias, const float* __restrict__ resid,
              float* __restrict__ C, __half* __restrict__ Ch,
              int M, int N, int K)
{
    extern __shared__ char sm[];
    uint32_t sb = smem_u32(sm);

    int tid  = threadIdx.x;
    int wid  = tid >> 5;
    int lane = tid & 31;
    int wm   = wid & 1;          // 0..1 (M)
    int wn   = wid >> 1;         // 0..1 (N)

    int row0 = blockIdx.y * 128, col0 = blockIdx.x * 128;
    const __half* pA = A + (size_t)row0 * K;
    const __half* pB = B + (size_t)col0 * K;

    int KB = K / KBLK;

    // cp.async: per tensor 128 rows x 4 chunks(16B); 4 chunks/thread
    int ld_r[4], ld_c[4];
    uint32_t ld_so[4];
    #pragma unroll
    for (int i = 0; i < 4; i++) {
        int idx = tid + (i << 7);
        ld_r[i] = idx >> 2;
        ld_c[i] = idx & 3;
        ld_so[i] = SMEM_SWZ64((uint32_t)(ld_r[i] * 64 + ld_c[i] * 16));
    }

    auto stage_base = [&](int kb) {
        return sb + (uint32_t)(kb % NSTAGE) * STAGE_BYTES;
    };

    auto load_stage = [&](int kb) {
        uint32_t base = stage_base(kb);
        int koff = kb * KBLK;
        #pragma unroll
        for (int i = 0; i < 4; i++) {
            size_t go = (size_t)ld_r[i] * K + koff + ld_c[i] * 8;
            CP_ASYNC16(base + ld_so[i],              (const void*)(pA + go));
            CP_ASYNC16(base + A_ST_BYTES + ld_so[i], (const void*)(pB + go));
        }
        CP_COMMIT();
    };

    // fragment load: A m64k16 (4 x4) + B n64k16 (4 x4) for one kk
    int a_lane_row = lane & 15;
    int a_lane_c   = (lane >> 4) << 4;        // byte offset within k16 (0 or 16)
    int b_lane_row = ((lane >> 4) << 3) + (lane & 7);
    int b_lane_c   = ((lane >> 3) & 1) << 4;
    auto ld_frags = [&](uint32_t base, int kk,
                        uint32_t (*ahb)[4], uint32_t (*bhb)[2]) {
        uint32_t sA = base, sB = base + A_ST_BYTES;
        int acol = kk * 32 + a_lane_c;
        #pragma unroll
        for (int mt = 0; mt < 4; mt++) {
            int row = wm * 64 + mt * 16 + a_lane_row;
            uint32_t off = SMEM_SWZ64((uint32_t)(row * 64 + acol));
            ldsm_x4(ahb[mt], sA + off);
        }
        int bcol = kk * 32 + b_lane_c;
        #pragma unroll
        for (int p = 0; p < 4; p++) {
            int brow = wn * 64 + p * 16 + b_lane_row;
            uint32_t off = SMEM_SWZ64((uint32_t)(brow * 64 + bcol));
            uint32_t t[4];
            ldsm_x4(t, sB + off);
            bhb[p*2][0] = t[0]; bhb[p*2][1] = t[1];
            bhb[p*2+1][0] = t[2]; bhb[p*2+1][1] = t[3];
        }
    };

    float acc[4][8][4];
    #pragma unroll
    for (int i = 0; i < 4; i++)
        #pragma unroll
        for (int j = 0; j < 8; j++)
            #pragma unroll
            for (int e = 0; e < 4; e++) acc[i][j][e] = 0.f;

    // prologue: fill NSTAGE-1 stages
    #pragma unroll
    for (int s = 0; s < NSTAGE - 1; s++) load_stage(s);
    CP_WAIT(NSTAGE - 2);      // stage 0 landed
    __syncthreads();

    uint32_t ah[2][4][4], bh[2][8][2];
    ld_frags(stage_base(0), 0, ah[0], bh[0]);

    for (int kb = 0; kb < KB; kb++) {
        #pragma unroll
        for (int kk = 0; kk < 2; kk++) {
            int cur = (kb * 2 + kk) & 1;
            int nxt = cur ^ 1;
            if (kk == 1) {
                if (kb + NSTAGE - 1 < KB) load_stage(kb + NSTAGE - 1);
                else                      CP_COMMIT();
                CP_WAIT(NSTAGE - 2);
                __syncthreads();
                if (kb + 1 < KB)
                    ld_frags(stage_base(kb + 1), 0, ah[nxt], bh[nxt]);
            } else {
                ld_frags(stage_base(kb), 1, ah[nxt], bh[nxt]);
            }
            #pragma unroll
            for (int mt = 0; mt < 4; mt++)
                #pragma unroll
                for (int nt = 0; nt < 8; nt++)
                    mma16816(acc[mt][nt], ah[cur][mt], bh[cur][nt]);
        }
    }

    // epilogue
    int g  = lane >> 2;
    int c2 = (lane & 3) * 2;
    #pragma unroll
    for (int mt = 0; mt < 4; mt++) {
        #pragma unroll
        for (int nt = 0; nt < 8; nt++) {
            int row = row0 + wm * 64 + mt * 16 + g;
            int col = col0 + wn * 64 + nt * 8 + c2;
            float d[4] = {acc[mt][nt][0], acc[mt][nt][1], acc[mt][nt][2], acc[mt][nt][3]};
            if (EPI >= 1) {
                float b0 = __ldg(&bias[col]), b1 = __ldg(&bias[col + 1]);
                d[0] += b0; d[1] += b1; d[2] += b0; d[3] += b1;
            }
            if (EPI == 1) {
                float2 r0 = *reinterpret_cast<const float2*>(&resid[(size_t)row * N + col]);
                float2 r1 = *reinterpret_cast<const float2*>(&resid[(size_t)(row + 8) * N + col]);
                d[0] += r0.x; d[1] += r0.y; d[2] += r1.x; d[3] += r1.y;
                *reinterpret_cast<float2*>(&C[(size_t)row * N + col])       = make_float2(d[0], d[1]);
                *reinterpret_cast<float2*>(&C[(size_t)(row + 8) * N + col]) = make_float2(d[2], d[3]);
            } else {
                if (EPI == 2) {
                    d[0] = gelu_exact(d[0]); d[1] = gelu_exact(d[1]);
                    d[2] = gelu_exact(d[2]); d[3] = gelu_exact(d[3]);
                }
                *reinterpret_cast<__half2*>(&Ch[(size_t)row * N + col]) =
                    __half2(__float2half(d[0]), __float2half(d[1]));
                *reinterpret_cast<__half2*>(&Ch[(size_t)(row + 8) * N + col]) =
                    __half2(__float2half(d[2]), __float2half(d[3]));
            }
        }
    }
}

// ---------------- tensor-core causal flash attention (fp16, exp2 softmax) ----------------
#define ATT_SMEM (8192 + 2 * 16384)   // 40960
#define SCALE_LOG2E 0.180336880f      // (1/8) * log2(e)

__global__ __launch_bounds__(128, 4)
void attn_mma(const __half* __restrict__ QKV,
              __half* __restrict__ O)
{
    extern __shared__ char sm[];
    uint32_t sb = smem_u32(sm);
    int tid = threadIdx.x, lane = tid & 31, w = tid >> 5;
    int bh = blockIdx.y, b = bh >> 4, h = bh & 15;
    int qt = blockIdx.x;
    const int QS = QKV_N;   // 3072

    // ---- issue Q loads ----
    {
        size_t q0 = (size_t)(b * SEQ + qt * 64) * QS + h * DK;
        #pragma unroll
        for (int i = 0; i < 4; i++) {
            int idx = tid + (i << 7);
            int r = idx >> 3, c = idx & 7;
            uint32_t so = SMEM_SWZ128((uint32_t)(r * 128 + c * 16));
            CP_ASYNC16(sb + so, (const void*)(QKV + q0 + (size_t)r * QS + c * 8));
        }
    }

    auto load_kv = [&](int kt) {
        uint32_t base = sb + 8192 + (kt & 1) * 16384;
        size_t k0 = (size_t)(b * SEQ + kt * 64) * QS + h * DK + DMODEL;
        size_t v0 = k0 + DMODEL;
        #pragma unroll
        for (int i = 0; i < 4; i++) {
            int idx = tid + (i << 7);
            int r = idx >> 3, c = idx & 7;
            uint32_t so = SMEM_SWZ128((uint32_t)(r * 128 + c * 16));
            CP_ASYNC16(base + so,        (const void*)(QKV + k0 + (size_t)r * QS + c * 8));
            CP_ASYNC16(base + 8192 + so, (const void*)(QKV + v0 + (size_t)r * QS + c * 8));
        }
        CP_COMMIT();
    };

    load_kv(0);
    CP_WAIT(0);
    __syncthreads();

    // ---- hoist Q fragments ----
    uint32_t qh[4][4];
    {
        int arow = w * 16 + (lane & 15);
        #pragma unroll
        for (int s = 0; s < 4; s++) {
            uint32_t off = SMEM_SWZ128((uint32_t)(arow * 128 + (s * 16 + ((lane >> 4) << 3)) * 2));
            ldsm_x4(qh[s], sb + off);
        }
    }

    float oacc[8][4];
    #pragma unroll
    for (int i = 0; i < 8; i++)
        #pragma unroll
        for (int e = 0; e < 4; e++) oacc[i][e] = 0.f;
    float m0 = -1e30f, m1 = -1e30f, l0 = 0.f, l1 = 0.f;

    int r0g = qt * 64 + w * 16 + (lane >> 2);
    int r1g = r0g + 8;

    for (int kt = 0; kt <= qt; kt++) {
        if (kt > 0) { CP_WAIT(0); __syncthreads(); }
        if (kt < qt) load_kv(kt + 1);

        uint32_t kbase = sb + 8192 + (kt & 1) * 16384;
        uint32_t vbase = kbase + 8192;

        // ---- S = Q K^T ----
        float sacc[8][4];
        #pragma unroll
        for (int i = 0; i < 8; i++)
            #pragma unroll
            for (int e = 0; e < 4; e++) sacc[i][e] = 0.f;

        int b_r = ((lane >> 4) << 3) + (lane & 7);
        #pragma unroll
        for (int s = 0; s < 4; s++) {
            int b_c2 = (s * 16 + (((lane >> 3) & 1) << 3)) * 2;
            #pragma unroll
            for (int np = 0; np < 4; np++) {
                uint32_t off = SMEM_SWZ128((uint32_t)((np * 16 + b_r) * 128 + b_c2));
                uint32_t th[4];
                ldsm_x4(th, kbase + off);
                uint32_t kh0[2] = {th[0], th[1]}, kh1[2] = {th[2], th[3]};
                mma16816(sacc[2*np],   qh[s], kh0);
                mma16816(sacc[2*np+1], qh[s], kh1);
            }
        }

        // ---- scale (log2 domain) + causal mask ----
        #pragma unroll
        for (int nt = 0; nt < 8; nt++)
            #pragma unroll
            for (int e = 0; e < 4; e++) sacc[nt][e] *= SCALE_LOG2E;
        if (kt == qt) {
            #pragma unroll
            for (int nt = 0; nt < 8; nt++) {
                int colb = kt * 64 + nt * 8 + 2 * (lane & 3);
                #pragma unroll
                for (int e = 0; e < 2; e++) {
                    if (colb + e > r0g) sacc[nt][e]     = -1e30f;
                    if (colb + e > r1g) sacc[nt][2 + e] = -1e30f;
                }
            }
        }

        // ---- online softmax (base-2) ----
        float mx0 = sacc[0][0], mx1 = sacc[0][2];
        #pragma unroll
        for (int nt = 0; nt < 8; nt++) {
            mx0 = fmaxf(mx0, fmaxf(sacc[nt][0], sacc[nt][1]));
            mx1 = fmaxf(mx1, fmaxf(sacc[nt][2], sacc[nt][3]));
        }
        mx0 = fmaxf(mx0, __shfl_xor_sync(0xffffffffu, mx0, 1));
        mx0 = fmaxf(mx0, __shfl_xor_sync(0xffffffffu, mx0, 2));
        mx1 = fmaxf(mx1, __shfl_xor_sync(0xffffffffu, mx1, 1));
        mx1 = fmaxf(mx1, __shfl_xor_sync(0xffffffffu, mx1, 2));
        float mn0 = fmaxf(m0, mx0), mn1 = fmaxf(m1, mx1);
        float a0 = exp2f(m0 - mn0), a1 = exp2f(m1 - mn1);

        float sum0 = 0.f, sum1 = 0.f;
        #pragma unroll
        for (int nt = 0; nt < 8; nt++) {
            sacc[nt][0] = exp2f(sacc[nt][0] - mn0);
            sacc[nt][1] = exp2f(sacc[nt][1] - mn0);
            sacc[nt][2] = exp2f(sacc[nt][2] - mn1);
            sacc[nt][3] = exp2f(sacc[nt][3] - mn1);
            sum0 += sacc[nt][0] + sacc[nt][1];
            sum1 += sacc[nt][2] + sacc[nt][3];
        }
        sum0 += __shfl_xor_sync(0xffffffffu, sum0, 1);
        sum0 += __shfl_xor_sync(0xffffffffu, sum0, 2);
        sum1 += __shfl_xor_sync(0xffffffffu, sum1, 1);
        sum1 += __shfl_xor_sync(0xffffffffu, sum1, 2);
        l0 = l0 * a0 + sum0;  m0 = mn0;
        l1 = l1 * a1 + sum1;  m1 = mn1;
        #pragma unroll
        for (int nt = 0; nt < 8; nt++) {
            oacc[nt][0] *= a0; oacc[nt][1] *= a0;
            oacc[nt][2] *= a1; oacc[nt][3] *= a1;
        }

        // ---- O += P V ----
        int r_in = lane & 7, sel = lane >> 3;
        #pragma unroll
        for (int s = 0; s < 4; s++) {
            uint32_t pah[4];
            #pragma unroll
            for (int half = 0; half < 2; half++) {
                float* pv = sacc[2*s + half];
                pah[half*2]   = pack2h(__float2half(pv[0]), __float2half(pv[1]));
                pah[half*2+1] = pack2h(__float2half(pv[2]), __float2half(pv[3]));
            }
            int vrow = s * 16 + (sel & 1) * 8 + r_in;
            #pragma unroll
            for (int np = 0; np < 4; np++) {
                int cb = np * 32 + (sel >> 1) * 16;
                uint32_t off = SMEM_SWZ128((uint32_t)(vrow * 128 + cb));
                uint32_t vh[4];
                ldsm_x4_t(vh, vbase + off);
                uint32_t vh0[2] = {vh[0], vh[1]}, vh1[2] = {vh[2], vh[3]};
                mma16816(oacc[2*np],   pah, vh0);
                mma16816(oacc[2*np+1], pah, vh1);
            }
        }
    }

    // ---- epilogue: O /= l, write fp16 ----
    float inv0 = 1.0f / l0, inv1 = 1.0f / l1;
    int grow = b * SEQ + r0g;
    #pragma unroll
    for (int nt = 0; nt < 8; nt++) {
        int col = h * DK + nt * 8 + 2 * (lane & 3);
        *reinterpret_cast<__half2*>(&O[(size_t)grow * DMODEL + col]) =
            __half2(__float2half(oacc[nt][0] * inv0), __float2half(oacc[nt][1] * inv0));
        *reinterpret_cast<__half2*>(&O[(size_t)(grow + 8) * DMODEL + col]) =
            __half2(__float2half(oacc[nt][2] * inv1), __float2half(oacc[nt][3] * inv1));
    }
}

// ---------------- launch ----------------
extern "C" void kernel_launch(void* const* d_in, const int* in_sizes, int n_in,
                              void* d_out, int out_size)
{
    const float* x     = (const float*)d_in[0];
    const float* ln1_g = (const float*)d_in[1];
    const float* ln1_b = (const float*)d_in[2];
    const float* w_q   = (const float*)d_in[3];
    const float* w_k   = (const float*)d_in[4];
    const float* w_v   = (const float*)d_in[5];
    const float* w_o   = (const float*)d_in[6];
    const float* b_o   = (const float*)d_in[7];
    const float* ln2_g = (const float*)d_in[8];
    const float* ln2_b = (const float*)d_in[9];
    const float* w1    = (const float*)d_in[10];
    const float* b1    = (const float*)d_in[11];
    const float* w2    = (const float*)d_in[12];
    const float* b2    = (const float*)d_in[13];
    float* out = (float*)d_out;

    __half *h,*qkv,*att,*ffn,*wqkv,*wo,*w1t,*w2t;
    float *x1;
    cudaGetSymbolAddress((void**)&h,    g_h);
    cudaGetSymbolAddress((void**)&qkv,  g_qkv);
    cudaGetSymbolAddress((void**)&att,  g_att);
    cudaGetSymbolAddress((void**)&x1,   g_x1);
    cudaGetSymbolAddress((void**)&ffn,  g_ffn);
    cudaGetSymbolAddress((void**)&wqkv, g_wqkvT);
    cudaGetSymbolAddress((void**)&wo,   g_woT);
    cudaGetSymbolAddress((void**)&w1t,  g_w1T);
    cudaGetSymbolAddress((void**)&w2t,  g_w2T);

    cudaFuncSetAttribute(attn_mma, cudaFuncAttributeMaxDynamicSharedMemorySize, ATT_SMEM);
    cudaFuncSetAttribute(mma_gemm<0>, cudaFuncAttributeMaxDynamicSharedMemorySize, MG_SMEM);
    cudaFuncSetAttribute(mma_gemm<1>, cudaFuncAttributeMaxDynamicSharedMemorySize, MG_SMEM);
    cudaFuncSetAttribute(mma_gemm<2>, cudaFuncAttributeMaxDynamicSharedMemorySize, MG_SMEM);

    dim3 tb(32, 8);
    dim3 gP(DMODEL / 128, ROWS / 128);    // (8, 64)
    dim3 gF1(FFN_DIM / 128, ROWS / 128);  // (32, 64)

    // ---- Launch 1: ALL weight transposes+quantize (6144 tiles of 64x32) ----
    {
        WArgs a;
        a.W[0] = w_q; a.T[0] = wqkv;                   a.K[0] = DMODEL;  a.N[0] = DMODEL;
        a.W[1] = w_k; a.T[1] = wqkv + DMODEL*DMODEL;   a.K[1] = DMODEL;  a.N[1] = DMODEL;
        a.W[2] = w_v; a.T[2] = wqkv + 2*DMODEL*DMODEL; a.K[2] = DMODEL;  a.N[2] = DMODEL;
        a.W[3] = w_o; a.T[3] = wo;                     a.K[3] = DMODEL;  a.N[3] = DMODEL;
        a.W[4] = w1;  a.T[4] = w1t;                    a.K[4] = DMODEL;  a.N[4] = FFN_DIM;
        a.W[5] = w2;  a.T[5] = w2t;                    a.K[5] = FFN_DIM; a.N[5] = DMODEL;
        int c = 0;
        for (int i = 0; i < 6; i++) {
            c += (a.K[i] / 64) * (a.N[i] / 32);
            a.cum[i] = c;
        }
        wsplit_all<<<a.cum[5], tb>>>(a);
    }
    // ---- Launch 2: LN1 ----
    ln_kernel<<<ROWS / 2, 256>>>(x, ln1_g, ln1_b, h);
    // ---- Launch 3: fused QKV projection -> fp16 ----
    mma_gemm<0><<<dim3(QKV_N/128, ROWS/128), 128, MG_SMEM>>>(h, wqkv,
        nullptr, nullptr, nullptr, qkv, ROWS, QKV_N, DMODEL);
    // ---- Launch 4 (profiled): tensor-core attention -> fp16 ----
    attn_mma<<<dim3(SEQ / 64, BATCH * NHEAD), 128, ATT_SMEM>>>(qkv, att);
    // ---- Launch 5: O projection + bias + residual -> x1 (fp32) ----
    mma_gemm<1><<<gP, 128, MG_SMEM>>>(att, wo, b_o, x, x1, nullptr, ROWS, DMODEL, DMODEL);
    // ---- Launch 6: LN2 ----
    ln_kernel<<<ROWS / 2, 256>>>(x1, ln2_g, ln2_b, h);
    // ---- Launch 7: FFN up + GELU -> fp16 ----
    mma_gemm<2><<<gF1, 128, MG_SMEM>>>(h, w1t, b1, nullptr, nullptr, ffn, ROWS, FFN_DIM, DMODEL);
    // ---- Launch 8: FFN down + bias + residual -> out ----
    mma_gemm<1><<<gP, 128, MG_SMEM>>>(ffn, w2t, b2, x1, out, nullptr, ROWS, DMODEL, FFN_DIM);
}

// round 15
// speedup vs baseline: 1.1049x; 1.0059x over previous
#include <cuda_runtime.h>
#include <cuda_fp16.h>
#include <math.h>
#include <stdint.h>

#define BATCH   16
#define SEQ     512
#define DMODEL  1024
#define NHEAD   16
#define DK      64
#define FFN_DIM 4096
#define ROWS    (BATCH * SEQ)        // 8192
#define QKV_N   (3 * DMODEL)         // 3072

// ---------------- scratch (device globals; no allocation) ----------------
__device__ __half g_h   [ROWS * DMODEL];
__device__ __half g_qkv [ROWS * QKV_N];
__device__ __half g_att [ROWS * DMODEL];
__device__ float  g_x1  [ROWS * DMODEL];
__device__ __half g_ffn [ROWS * FFN_DIM];
// transposed fp16 weights: T[N,K]
__device__ __half g_wqkvT[QKV_N*DMODEL];
__device__ __half g_woT  [DMODEL*DMODEL];
__device__ __half g_w1T  [DMODEL*FFN_DIM];
__device__ __half g_w2T  [FFN_DIM*DMODEL];

// ---------------- helpers ----------------
__device__ __forceinline__ uint32_t smem_u32(const void* p) {
    uint32_t a;
    asm("{ .reg .u64 t; cvta.to.shared.u64 t, %1; cvt.u32.u64 %0, t; }" : "=r"(a) : "l"(p));
    return a;
}
#define CP_ASYNC16(dst, src) \
    asm volatile("cp.async.cg.shared.global [%0], [%1], 16;" :: "r"(dst), "l"(src) : "memory")
#define CP_COMMIT() asm volatile("cp.async.commit_group;" ::: "memory")
#define CP_WAIT(n)  asm volatile("cp.async.wait_group %0;" :: "n"(n) : "memory")
#define SMEM_SWZ128(off) ((off) ^ (((off) >> 3) & 0x70))
#define SMEM_SWZ64(off)  ((off) ^ (((off) >> 3) & 0x30))

__device__ __forceinline__ void ldsm_x4(uint32_t* r, uint32_t addr) {
    asm volatile("ldmatrix.sync.aligned.m8n8.x4.shared.b16 {%0,%1,%2,%3}, [%4];"
        : "=r"(r[0]), "=r"(r[1]), "=r"(r[2]), "=r"(r[3]) : "r"(addr));
}
__device__ __forceinline__ void ldsm_x4_t(uint32_t* r, uint32_t addr) {
    asm volatile("ldmatrix.sync.aligned.m8n8.x4.trans.shared.b16 {%0,%1,%2,%3}, [%4];"
        : "=r"(r[0]), "=r"(r[1]), "=r"(r[2]), "=r"(r[3]) : "r"(addr));
}
__device__ __forceinline__ void mma16816(float* d, const uint32_t* a, const uint32_t* b) {
    asm volatile("mma.sync.aligned.m16n8k16.row.col.f32.f16.f16.f32 "
        "{%0,%1,%2,%3}, {%4,%5,%6,%7}, {%8,%9}, {%0,%1,%2,%3};"
        : "+f"(d[0]), "+f"(d[1]), "+f"(d[2]), "+f"(d[3])
        : "r"(a[0]), "r"(a[1]), "r"(a[2]), "r"(a[3]), "r"(b[0]), "r"(b[1]));
}

__device__ __forceinline__ float gelu_exact(float v) {
    return 0.5f * v * (1.0f + erff(v * 0.70710678118654752f));
}
__device__ __forceinline__ uint32_t pack2h(__half a, __half b) {
    __half2 t(a, b);
    return *reinterpret_cast<uint32_t*>(&t);
}

// ---------------- fused weight transpose + fp16 quantize (ALL weights, 1 launch) ----------------
// 64(k) x 32(n) tiles; half2 writes along K -> full 128B write transactions.
struct WArgs {
    const float* W[6];
    __half*      T[6];
    int K[6], N[6];
    int cum[6];     // cumulative tile counts
};

__global__ void wsplit_all(WArgs a)
{
    __shared__ float t[64][33];
    int idx = blockIdx.x;
    int m = 0;
    #pragma unroll
    for (int i = 0; i < 5; i++) m += (idx >= a.cum[i]);
    if (m > 0) idx -= a.cum[m - 1];
    const float* W = a.W[m];
    __half* T = a.T[m];
    int K = a.K[m], N = a.N[m];
    int ntx = N >> 5;
    int n0 = (idx % ntx) * 32, k0 = (idx / ntx) * 64;

    int tx = threadIdx.x, ty = threadIdx.y;
    #pragma unroll
    for (int i = 0; i < 8; i++)
        t[ty + 8*i][tx] = W[(size_t)(k0 + ty + 8*i) * N + n0 + tx];
    __syncthreads();
    #pragma unroll
    for (int i = 0; i < 4; i++) {
        int ny = ty * 4 + i;
        __half2 hv(__float2half(t[tx*2][ny]), __float2half(t[tx*2 + 1][ny]));
        *reinterpret_cast<__half2*>(&T[(size_t)(n0 + ny) * K + k0 + tx*2]) = hv;
    }
}

// ---------------- LayerNorm: 2 rows per block (one per 128-thread group) ----------------
__global__ void ln_kernel(const float* __restrict__ x,
                          const float* __restrict__ g,
                          const float* __restrict__ b,
                          __half* __restrict__ oh)
{
    int grp = threadIdx.x >> 7;            // 0..1
    int t   = threadIdx.x & 127;           // 0..127, handles 2 float4 each
    int row = blockIdx.x * 2 + grp;

    const float4* xr = reinterpret_cast<const float4*>(x + (size_t)row * DMODEL);
    float4 v0 = xr[t], v1 = xr[t + 128];
    float s  = v0.x + v0.y + v0.z + v0.w + v1.x + v1.y + v1.z + v1.w;
    float sq = v0.x*v0.x + v0.y*v0.y + v0.z*v0.z + v0.w*v0.w
             + v1.x*v1.x + v1.y*v1.y + v1.z*v1.z + v1.w*v1.w;

    __shared__ float red_s[2][4], red_q[2][4];
    for (int o = 16; o > 0; o >>= 1) {
        s  += __shfl_xor_sync(0xffffffffu, s,  o);
        sq += __shfl_xor_sync(0xffffffffu, sq, o);
    }
    int wid = t >> 5, lid = t & 31;
    if (lid == 0) { red_s[grp][wid] = s; red_q[grp][wid] = sq; }
    __syncthreads();
    float ss = red_s[grp][0] + red_s[grp][1] + red_s[grp][2] + red_s[grp][3];
    float qq = red_q[grp][0] + red_q[grp][1] + red_q[grp][2] + red_q[grp][3];

    float mean = ss * (1.0f / DMODEL);
    float var  = qq * (1.0f / DMODEL) - mean * mean;
    float rstd = rsqrtf(var + 1e-5f);

    float4 gv0 = reinterpret_cast<const float4*>(g)[t];
    float4 bv0 = reinterpret_cast<const float4*>(b)[t];
    float4 gv1 = reinterpret_cast<const float4*>(g)[t + 128];
    float4 bv1 = reinterpret_cast<const float4*>(b)[t + 128];
    float o0 = (v0.x - mean) * rstd * gv0.x + bv0.x;
    float o1 = (v0.y - mean) * rstd * gv0.y + bv0.y;
    float o2 = (v0.z - mean) * rstd * gv0.z + bv0.z;
    float o3 = (v0.w - mean) * rstd * gv0.w + bv0.w;
    float o4 = (v1.x - mean) * rstd * gv1.x + bv1.x;
    float o5 = (v1.y - mean) * rstd * gv1.y + bv1.y;
    float o6 = (v1.z - mean) * rstd * gv1.z + bv1.z;
    float o7 = (v1.w - mean) * rstd * gv1.w + bv1.w;
    __half2* ph = reinterpret_cast<__half2*>(oh + (size_t)row * DMODEL);
    ph[t*2]       = __half2(__float2half(o0), __float2half(o1));
    ph[t*2+1]     = __half2(__float2half(o2), __float2half(o3));
    ph[256 + t*2]   = __half2(__float2half(o4), __float2half(o5));
    ph[256 + t*2+1] = __half2(__float2half(o6), __float2half(o7));
}

// ---------------- CUTLASS-shape fp16 GEMM (R11/R13 mainloop, 5 stages) ----------------
// CTA 128x128, 4 warps (2M x 2N), warp tile 64x64, KBLK=32, 5 stages, 2 CTAs/SM.
// EPI: 0 = fp16 C; 1 = +bias +resid -> fp32 C; 2 = +bias, GELU -> fp16 C
#define KBLK 32
#define A_ST_BYTES 8192              // 128 rows x 64B
#define STAGE_BYTES 16384            // A 8K | B 8K
#define NSTAGE 5
#define MG_SMEM (NSTAGE * STAGE_BYTES)   // 81920

template<int EPI>
__global__ __launch_bounds__(128, 2)
void mma_gemm(const __half* __restrict__ A, const __half* __restrict__ B,
              const float* __restrict__ bias, const float* __restrict__ resid,
              float* __restrict__ C, __half* __restrict__ Ch,
              int M, int N, int K)
{
    extern __shared__ char sm[];
    uint32_t sb = smem_u32(sm);

    int tid  = threadIdx.x;
    int wid  = tid >> 5;
    int lane = tid & 31;
    int wm   = wid & 1;          // 0..1 (M)
    int wn   = wid >> 1;         // 0..1 (N)

    int row0 = blockIdx.y * 128, col0 = blockIdx.x * 128;
    const __half* pA = A + (size_t)row0 * K;
    const __half* pB = B + (size_t)col0 * K;

    int KB = K / KBLK;

    // cp.async: per tensor 128 rows x 4 chunks(16B); 4 chunks/thread
    int ld_r[4], ld_c[4];
    uint32_t ld_so[4];
    #pragma unroll
    for (int i = 0; i < 4; i++) {
        int idx = tid + (i << 7);
        ld_r[i] = idx >> 2;
        ld_c[i] = idx & 3;
        ld_so[i] = SMEM_SWZ64((uint32_t)(ld_r[i] * 64 + ld_c[i] * 16));
    }

    auto stage_base = [&](int kb) {
        return sb + (uint32_t)(kb % NSTAGE) * STAGE_BYTES;
    };

    auto load_stage = [&](int kb) {
        uint32_t base = stage_base(kb);
        int koff = kb * KBLK;
        #pragma unroll
        for (int i = 0; i < 4; i++) {
            size_t go = (size_t)ld_r[i] * K + koff + ld_c[i] * 8;
            CP_ASYNC16(base + ld_so[i],              (const void*)(pA + go));
            CP_ASYNC16(base + A_ST_BYTES + ld_so[i], (const void*)(pB + go));
        }
        CP_COMMIT();
    };

    // fragment load: A m64k16 (4 x4) + B n64k16 (4 x4) for one kk
    int a_lane_row = lane & 15;
    int a_lane_c   = (lane >> 4) << 4;        // byte offset within k16 (0 or 16)
    int b_lane_row = ((lane >> 4) << 3) + (lane & 7);
    int b_lane_c   = ((lane >> 3) & 1) << 4;
    auto ld_frags = [&](uint32_t base, int kk,
                        uint32_t (*ahb)[4], uint32_t (*bhb)[2]) {
        uint32_t sA = base, sB = base + A_ST_BYTES;
        int acol = kk * 32 + a_lane_c;
        #pragma unroll
        for (int mt = 0; mt < 4; mt++) {
            int row = wm * 64 + mt * 16 + a_lane_row;
            uint32_t off = SMEM_SWZ64((uint32_t)(row * 64 + acol));
            ldsm_x4(ahb[mt], sA + off);
        }
        int bcol = kk * 32 + b_lane_c;
        #pragma unroll
        for (int p = 0; p < 4; p++) {
            int brow = wn * 64 + p * 16 + b_lane_row;
            uint32_t off = SMEM_SWZ64((uint32_t)(brow * 64 + bcol));
            uint32_t t[4];
            ldsm_x4(t, sB + off);
            bhb[p*2][0] = t[0]; bhb[p*2][1] = t[1];
            bhb[p*2+1][0] = t[2]; bhb[p*2+1][1] = t[3];
        }
    };

    float acc[4][8][4];
    #pragma unroll
    for (int i = 0; i < 4; i++)
        #pragma unroll
        for (int j = 0; j < 8; j++)
            #pragma unroll
            for (int e = 0; e < 4; e++) acc[i][j][e] = 0.f;

    // prologue: fill NSTAGE-1 stages
    #pragma unroll
    for (int s = 0; s < NSTAGE - 1; s++) load_stage(s);
    CP_WAIT(NSTAGE - 2);      // stage 0 landed
    __syncthreads();

    uint32_t ah[2][4][4], bh[2][8][2];
    ld_frags(stage_base(0), 0, ah[0], bh[0]);

    for (int kb = 0; kb < KB; kb++) {
        #pragma unroll
        for (int kk = 0; kk < 2; kk++) {
            int cur = (kb * 2 + kk) & 1;
            int nxt = cur ^ 1;
            if (kk == 1) {
                if (kb + NSTAGE - 1 < KB) load_stage(kb + NSTAGE - 1);
                else                      CP_COMMIT();
                CP_WAIT(NSTAGE - 2);
                __syncthreads();
                if (kb + 1 < KB)
                    ld_frags(stage_base(kb + 1), 0, ah[nxt], bh[nxt]);
            } else {
                ld_frags(stage_base(kb), 1, ah[nxt], bh[nxt]);
            }
            #pragma unroll
            for (int mt = 0; mt < 4; mt++)
                #pragma unroll
                for (int nt = 0; nt < 8; nt++)
                    mma16816(acc[mt][nt], ah[cur][mt], bh[cur][nt]);
        }
    }

    // epilogue
    int g  = lane >> 2;
    int c2 = (lane & 3) * 2;
    #pragma unroll
    for (int mt = 0; mt < 4; mt++) {
        #pragma unroll
        for (int nt = 0; nt < 8; nt++) {
            int row = row0 + wm * 64 + mt * 16 + g;
            int col = col0 + wn * 64 + nt * 8 + c2;
            float d[4] = {acc[mt][nt][0], acc[mt][nt][1], acc[mt][nt][2], acc[mt][nt][3]};
            if (EPI >= 1) {
                float b0 = __ldg(&bias[col]), b1 = __ldg(&bias[col + 1]);
                d[0] += b0; d[1] += b1; d[2] += b0; d[3] += b1;
            }
            if (EPI == 1) {
                float2 r0 = *reinterpret_cast<const float2*>(&resid[(size_t)row * N + col]);
                float2 r1 = *reinterpret_cast<const float2*>(&resid[(size_t)(row + 8) * N + col]);
                d[0] += r0.x; d[1] += r0.y; d[2] += r1.x; d[3] += r1.y;
                *reinterpret_cast<float2*>(&C[(size_t)row * N + col])       = make_float2(d[0], d[1]);
                *reinterpret_cast<float2*>(&C[(size_t)(row + 8) * N + col]) = make_float2(d[2], d[3]);
            } else {
                if (EPI == 2) {
                    d[0] = gelu_exact(d[0]); d[1] = gelu_exact(d[1]);
                    d[2] = gelu_exact(d[2]); d[3] = gelu_exact(d[3]);
                }
                *reinterpret_cast<__half2*>(&Ch[(size_t)row * N + col]) =
                    __half2(__float2half(d[0]), __float2half(d[1]));
                *reinterpret_cast<__half2*>(&Ch[(size_t)(row + 8) * N + col]) =
                    __half2(__float2half(d[2]), __float2half(d[3]));
            }
        }
    }
}

// ---------------- tensor-core causal flash attention (fp16, exp2 softmax) ----------------
#define ATT_SMEM (8192 + 2 * 16384)   // 40960
#define SCALE_LOG2E 0.180336880f      // (1/8) * log2(e)

__global__ __launch_bounds__(128, 4)
void attn_mma(const __half* __restrict__ QKV,
              __half* __restrict__ O)
{
    extern __shared__ char sm[];
    uint32_t sb = smem_u32(sm);
    int tid = threadIdx.x, lane = tid & 31, w = tid >> 5;
    int bh = blockIdx.y, b = bh >> 4, h = bh & 15;
    int qt = gridDim.x - 1 - blockIdx.x;   // longest-first scheduling
    const int QS = QKV_N;   // 3072

    // ---- issue Q loads ----
    {
        size_t q0 = (size_t)(b * SEQ + qt * 64) * QS + h * DK;
        #pragma unroll
        for (int i = 0; i < 4; i++) {
            int idx = tid + (i << 7);
            int r = idx >> 3, c = idx & 7;
            uint32_t so = SMEM_SWZ128((uint32_t)(r * 128 + c * 16));
            CP_ASYNC16(sb + so, (const void*)(QKV + q0 + (size_t)r * QS + c * 8));
        }
    }

    auto load_kv = [&](int kt) {
        uint32_t base = sb + 8192 + (kt & 1) * 16384;
        size_t k0 = (size_t)(b * SEQ + kt * 64) * QS + h * DK + DMODEL;
        size_t v0 = k0 + DMODEL;
        #pragma unroll
        for (int i = 0; i < 4; i++) {
            int idx = tid + (i << 7);
            int r = idx >> 3, c = idx & 7;
            uint32_t so = SMEM_SWZ128((uint32_t)(r * 128 + c * 16));
            CP_ASYNC16(base + so,        (const void*)(QKV + k0 + (size_t)r * QS + c * 8));
            CP_ASYNC16(base + 8192 + so, (const void*)(QKV + v0 + (size_t)r * QS + c * 8));
        }
        CP_COMMIT();
    };

    load_kv(0);
    CP_WAIT(0);
    __syncthreads();

    // ---- hoist Q fragments ----
    uint32_t qh[4][4];
    {
        int arow = w * 16 + (lane & 15);
        #pragma unroll
        for (int s = 0; s < 4; s++) {
            uint32_t off = SMEM_SWZ128((uint32_t)(arow * 128 + (s * 16 + ((lane >> 4) << 3)) * 2));
            ldsm_x4(qh[s], sb + off);
        }
    }

    float oacc[8][4];
    #pragma unroll
    for (int i = 0; i < 8; i++)
        #pragma unroll
        for (int e = 0; e < 4; e++) oacc[i][e] = 0.f;
    float m0 = -1e30f, m1 = -1e30f, l0 = 0.f, l1 = 0.f;

    int r0g = qt * 64 + w * 16 + (lane >> 2);
    int r1g = r0g + 8;

    for (int kt = 0; kt <= qt; kt++) {
        if (kt > 0) { CP_WAIT(0); __syncthreads(); }
        if (kt < qt) load_kv(kt + 1);

        uint32_t kbase = sb + 8192 + (kt & 1) * 16384;
        uint32_t vbase = kbase + 8192;

        // ---- S = Q K^T ----
        float sacc[8][4];
        #pragma unroll
        for (int i = 0; i < 8; i++)
            #pragma unroll
            for (int e = 0; e < 4; e++) sacc[i][e] = 0.f;

        int b_r = ((lane >> 4) << 3) + (lane & 7);
        #pragma unroll
        for (int s = 0; s < 4; s++) {
            int b_c2 = (s * 16 + (((lane >> 3) & 1) << 3)) * 2;
            #pragma unroll
            for (int np = 0; np < 4; np++) {
                uint32_t off = SMEM_SWZ128((uint32_t)((np * 16 + b_r) * 128 + b_c2));
                uint32_t th[4];
                ldsm_x4(th, kbase + off);
                uint32_t kh0[2] = {th[0], th[1]}, kh1[2] = {th[2], th[3]};
                mma16816(sacc[2*np],   qh[s], kh0);
                mma16816(sacc[2*np+1], qh[s], kh1);
            }
        }

        // ---- scale (log2 domain) + causal mask ----
        #pragma unroll
        for (int nt = 0; nt < 8; nt++)
            #pragma unroll
            for (int e = 0; e < 4; e++) sacc[nt][e] *= SCALE_LOG2E;
        if (kt == qt) {
            #pragma unroll
            for (int nt = 0; nt < 8; nt++) {
                int colb = kt * 64 + nt * 8 + 2 * (lane & 3);
                #pragma unroll
                for (int e = 0; e < 2; e++) {
                    if (colb + e > r0g) sacc[nt][e]     = -1e30f;
                    if (colb + e > r1g) sacc[nt][2 + e] = -1e30f;
                }
            }
        }

        // ---- online softmax (base-2) ----
        float mx0 = sacc[0][0], mx1 = sacc[0][2];
        #pragma unroll
        for (int nt = 0; nt < 8; nt++) {
            mx0 = fmaxf(mx0, fmaxf(sacc[nt][0], sacc[nt][1]));
            mx1 = fmaxf(mx1, fmaxf(sacc[nt][2], sacc[nt][3]));
        }
        mx0 = fmaxf(mx0, __shfl_xor_sync(0xffffffffu, mx0, 1));
        mx0 = fmaxf(mx0, __shfl_xor_sync(0xffffffffu, mx0, 2));
        mx1 = fmaxf(mx1, __shfl_xor_sync(0xffffffffu, mx1, 1));
        mx1 = fmaxf(mx1, __shfl_xor_sync(0xffffffffu, mx1, 2));
        float mn0 = fmaxf(m0, mx0), mn1 = fmaxf(m1, mx1);
        float a0 = exp2f(m0 - mn0), a1 = exp2f(m1 - mn1);

        float sum0 = 0.f, sum1 = 0.f;
        #pragma unroll
        for (int nt = 0; nt < 8; nt++) {
            sacc[nt][0] = exp2f(sacc[nt][0] - mn0);
            sacc[nt][1] = exp2f(sacc[nt][1] - mn0);
            sacc[nt][2] = exp2f(sacc[nt][2] - mn1);
            sacc[nt][3] = exp2f(sacc[nt][3] - mn1);
            sum0 += sacc[nt][0] + sacc[nt][1];
            sum1 += sacc[nt][2] + sacc[nt][3];
        }
        sum0 += __shfl_xor_sync(0xffffffffu, sum0, 1);
        sum0 += __shfl_xor_sync(0xffffffffu, sum0, 2);
        sum1 += __shfl_xor_sync(0xffffffffu, sum1, 1);
        sum1 += __shfl_xor_sync(0xffffffffu, sum1, 2);
        l0 = l0 * a0 + sum0;  m0 = mn0;
        l1 = l1 * a1 + sum1;  m1 = mn1;
        #pragma unroll
        for (int nt = 0; nt < 8; nt++) {
            oacc[nt][0] *= a0; oacc[nt][1] *= a0;
            oacc[nt][2] *= a1; oacc[nt][3] *= a1;
        }

        // ---- O += P V ----
        int r_in = lane & 7, sel = lane >> 3;
        #pragma unroll
        for (int s = 0; s < 4; s++) {
            uint32_t pah[4];
            #pragma unroll
            for (int half = 0; half < 2; half++) {
                float* pv = sacc[2*s + half];
                pah[half*2]   = pack2h(__float2half(pv[0]), __float2half(pv[1]));
                pah[half*2+1] = pack2h(__float2half(pv[2]), __float2half(pv[3]));
            }
            int vrow = s * 16 + (sel & 1) * 8 + r_in;
            #pragma unroll
            for (int np = 0; np < 4; np++) {
                int cb = np * 32 + (sel >> 1) * 16;
                uint32_t off = SMEM_SWZ128((uint32_t)(vrow * 128 + cb));
                uint32_t vh[4];
                ldsm_x4_t(vh, vbase + off);
                uint32_t vh0[2] = {vh[0], vh[1]}, vh1[2] = {vh[2], vh[3]};
                mma16816(oacc[2*np],   pah, vh0);
                mma16816(oacc[2*np+1], pah, vh1);
            }
        }
    }

    // ---- epilogue: O /= l, write fp16 ----
    float inv0 = 1.0f / l0, inv1 = 1.0f / l1;
    int grow = b * SEQ + r0g;
    #pragma unroll
    for (int nt = 0; nt < 8; nt++) {
        int col = h * DK + nt * 8 + 2 * (lane & 3);
        *reinterpret_cast<__half2*>(&O[(size_t)grow * DMODEL + col]) =
            __half2(__float2half(oacc[nt][0] * inv0), __float2half(oacc[nt][1] * inv0));
        *reinterpret_cast<__half2*>(&O[(size_t)(grow + 8) * DMODEL + col]) =
            __half2(__float2half(oacc[nt][2] * inv1), __float2half(oacc[nt][3] * inv1));
    }
}

// ---------------- launch ----------------
extern "C" void kernel_launch(void* const* d_in, const int* in_sizes, int n_in,
                              void* d_out, int out_size)
{
    const float* x     = (const float*)d_in[0];
    const float* ln1_g = (const float*)d_in[1];
    const float* ln1_b = (const float*)d_in[2];
    const float* w_q   = (const float*)d_in[3];
    const float* w_k   = (const float*)d_in[4];
    const float* w_v   = (const float*)d_in[5];
    const float* w_o   = (const float*)d_in[6];
    const float* b_o   = (const float*)d_in[7];
    const float* ln2_g = (const float*)d_in[8];
    const float* ln2_b = (const float*)d_in[9];
    const float* w1    = (const float*)d_in[10];
    const float* b1    = (const float*)d_in[11];
    const float* w2    = (const float*)d_in[12];
    const float* b2    = (const float*)d_in[13];
    float* out = (float*)d_out;

    __half *h,*qkv,*att,*ffn,*wqkv,*wo,*w1t,*w2t;
    float *x1;
    cudaGetSymbolAddress((void**)&h,    g_h);
    cudaGetSymbolAddress((void**)&qkv,  g_qkv);
    cudaGetSymbolAddress((void**)&att,  g_att);
    cudaGetSymbolAddress((void**)&x1,   g_x1);
    cudaGetSymbolAddress((void**)&ffn,  g_ffn);
    cudaGetSymbolAddress((void**)&wqkv, g_wqkvT);
    cudaGetSymbolAddress((void**)&wo,   g_woT);
    cudaGetSymbolAddress((void**)&w1t,  g_w1T);
    cudaGetSymbolAddress((void**)&w2t,  g_w2T);

    cudaFuncSetAttribute(attn_mma, cudaFuncAttributeMaxDynamicSharedMemorySize, ATT_SMEM);
    cudaFuncSetAttribute(mma_gemm<0>, cudaFuncAttributeMaxDynamicSharedMemorySize, MG_SMEM);
    cudaFuncSetAttribute(mma_gemm<1>, cudaFuncAttributeMaxDynamicSharedMemorySize, MG_SMEM);
    cudaFuncSetAttribute(mma_gemm<2>, cudaFuncAttributeMaxDynamicSharedMemorySize, MG_SMEM);

    dim3 tb(32, 8);
    dim3 gP(DMODEL / 128, ROWS / 128);    // (8, 64)
    dim3 gF1(FFN_DIM / 128, ROWS / 128);  // (32, 64)

    // ---- Launch 1: ALL weight transposes+quantize (6144 tiles of 64x32) ----
    {
        WArgs a;
        a.W[0] = w_q; a.T[0] = wqkv;                   a.K[0] = DMODEL;  a.N[0] = DMODEL;
        a.W[1] = w_k; a.T[1] = wqkv + DMODEL*DMODEL;   a.K[1] = DMODEL;  a.N[1] = DMODEL;
        a.W[2] = w_v; a.T[2] = wqkv + 2*DMODEL*DMODEL; a.K[2] = DMODEL;  a.N[2] = DMODEL;
        a.W[3] = w_o; a.T[3] = wo;                     a.K[3] = DMODEL;  a.N[3] = DMODEL;
        a.W[4] = w1;  a.T[4] = w1t;                    a.K[4] = DMODEL;  a.N[4] = FFN_DIM;
        a.W[5] = w2;  a.T[5] = w2t;                    a.K[5] = FFN_DIM; a.N[5] = DMODEL;
        int c = 0;
        for (int i = 0; i < 6; i++) {
            c += (a.K[i] / 64) * (a.N[i] / 32);
            a.cum[i] = c;
        }
        wsplit_all<<<a.cum[5], tb>>>(a);
    }
    // ---- Launch 2: LN1 ----
    ln_kernel<<<ROWS / 2, 256>>>(x, ln1_g, ln1_b, h);
    // ---- Launch 3: fused QKV projection -> fp16 ----
    mma_gemm<0><<<dim3(QKV_N/128, ROWS/128), 128, MG_SMEM>>>(h, wqkv,
        nullptr, nullptr, nullptr, qkv, ROWS, QKV_N, DMODEL);
    // ---- Launch 4: tensor-core attention -> fp16 ----
    attn_mma<<<dim3(SEQ / 64, BATCH * NHEAD), 128, ATT_SMEM>>>(qkv, att);
    // ---- Launch 5: O projection + bias + residual -> x1 (fp32) ----
    mma_gemm<1><<<gP, 128, MG_SMEM>>>(att, wo, b_o, x, x1, nullptr, ROWS, DMODEL, DMODEL);
    // ---- Launch 6: LN2 ----
    ln_kernel<<<ROWS / 2, 256>>>(x1, ln2_g, ln2_b, h);
    // ---- Launch 7: FFN up + GELU -> fp16 ----
    mma_gemm<2><<<gF1, 128, MG_SMEM>>>(h, w1t, b1, nullptr, nullptr, ffn, ROWS, FFN_DIM, DMODEL);
    // ---- Launch 8: FFN down + bias + residual -> out ----
    mma_gemm<1><<<gP, 128, MG_SMEM>>>(ffn, w2t, b2, x1, out, nullptr, ROWS, DMODEL, FFN_DIM);
}

// round 17
// speedup vs baseline: 1.1242x; 1.0175x over previous
#include <cuda_runtime.h>
#include <cuda_fp16.h>
#include <math.h>
#include <stdint.h>

#define BATCH   16
#define SEQ     512
#define DMODEL  1024
#define NHEAD   16
#define DK      64
#define FFN_DIM 4096
#define ROWS    (BATCH * SEQ)        // 8192
#define QKV_N   (3 * DMODEL)         // 3072

// ---------------- scratch (device globals; no allocation) ----------------
__device__ __half g_h   [ROWS * DMODEL];
__device__ __half g_qkv [ROWS * QKV_N];
__device__ __half g_att [ROWS * DMODEL];
__device__ float  g_x1  [ROWS * DMODEL];
__device__ __half g_ffn [ROWS * FFN_DIM];
// transposed fp16 weights: T[N,K]
__device__ __half g_wqkvT[QKV_N*DMODEL];
__device__ __half g_woT  [DMODEL*DMODEL];
__device__ __half g_w1T  [DMODEL*FFN_DIM];
__device__ __half g_w2T  [FFN_DIM*DMODEL];

// ---------------- helpers ----------------
__device__ __forceinline__ uint32_t smem_u32(const void* p) {
    uint32_t a;
    asm("{ .reg .u64 t; cvta.to.shared.u64 t, %1; cvt.u32.u64 %0, t; }" : "=r"(a) : "l"(p));
    return a;
}
#define CP_ASYNC16(dst, src) \
    asm volatile("cp.async.cg.shared.global [%0], [%1], 16;" :: "r"(dst), "l"(src) : "memory")
#define CP_COMMIT() asm volatile("cp.async.commit_group;" ::: "memory")
#define CP_WAIT(n)  asm volatile("cp.async.wait_group %0;" :: "n"(n) : "memory")
#define SMEM_SWZ128(off) ((off) ^ (((off) >> 3) & 0x70))
#define SMEM_SWZ64(off)  ((off) ^ (((off) >> 3) & 0x30))

__device__ __forceinline__ void ldsm_x4(uint32_t* r, uint32_t addr) {
    asm volatile("ldmatrix.sync.aligned.m8n8.x4.shared.b16 {%0,%1,%2,%3}, [%4];"
        : "=r"(r[0]), "=r"(r[1]), "=r"(r[2]), "=r"(r[3]) : "r"(addr));
}
__device__ __forceinline__ void ldsm_x4_t(uint32_t* r, uint32_t addr) {
    asm volatile("ldmatrix.sync.aligned.m8n8.x4.trans.shared.b16 {%0,%1,%2,%3}, [%4];"
        : "=r"(r[0]), "=r"(r[1]), "=r"(r[2]), "=r"(r[3]) : "r"(addr));
}
__device__ __forceinline__ void mma16816(float* d, const uint32_t* a, const uint32_t* b) {
    asm volatile("mma.sync.aligned.m16n8k16.row.col.f32.f16.f16.f32 "
        "{%0,%1,%2,%3}, {%4,%5,%6,%7}, {%8,%9}, {%0,%1,%2,%3};"
        : "+f"(d[0]), "+f"(d[1]), "+f"(d[2]), "+f"(d[3])
        : "r"(a[0]), "r"(a[1]), "r"(a[2]), "r"(a[3]), "r"(b[0]), "r"(b[1]));
}

__device__ __forceinline__ float gelu_exact(float v) {
    return 0.5f * v * (1.0f + erff(v * 0.70710678118654752f));
}
__device__ __forceinline__ uint32_t pack2h(__half a, __half b) {
    __half2 t(a, b);
    return *reinterpret_cast<uint32_t*>(&t);
}

// ---------------- fused weight transpose + fp16 quantize (ALL weights, 1 launch) ----------------
struct WArgs {
    const float* W[6];
    __half*      T[6];
    int K[6], N[6];
    int cum[6];
};

__global__ void wsplit_all(WArgs a)
{
    __shared__ float t[64][33];
    int idx = blockIdx.x;
    int m = 0;
    #pragma unroll
    for (int i = 0; i < 5; i++) m += (idx >= a.cum[i]);
    if (m > 0) idx -= a.cum[m - 1];
    const float* W = a.W[m];
    __half* T = a.T[m];
    int K = a.K[m], N = a.N[m];
    int ntx = N >> 5;
    int n0 = (idx % ntx) * 32, k0 = (idx / ntx) * 64;

    int tx = threadIdx.x, ty = threadIdx.y;
    #pragma unroll
    for (int i = 0; i < 8; i++)
        t[ty + 8*i][tx] = W[(size_t)(k0 + ty + 8*i) * N + n0 + tx];
    __syncthreads();
    #pragma unroll
    for (int i = 0; i < 4; i++) {
        int ny = ty * 4 + i;
        __half2 hv(__float2half(t[tx*2][ny]), __float2half(t[tx*2 + 1][ny]));
        *reinterpret_cast<__half2*>(&T[(size_t)(n0 + ny) * K + k0 + tx*2]) = hv;
    }
}

// ---------------- LayerNorm: 2 rows per block ----------------
__global__ void ln_kernel(const float* __restrict__ x,
                          const float* __restrict__ g,
                          const float* __restrict__ b,
                          __half* __restrict__ oh)
{
    int grp = threadIdx.x >> 7;
    int t   = threadIdx.x & 127;
    int row = blockIdx.x * 2 + grp;

    const float4* xr = reinterpret_cast<const float4*>(x + (size_t)row * DMODEL);
    float4 v0 = xr[t], v1 = xr[t + 128];
    float s  = v0.x + v0.y + v0.z + v0.w + v1.x + v1.y + v1.z + v1.w;
    float sq = v0.x*v0.x + v0.y*v0.y + v0.z*v0.z + v0.w*v0.w
             + v1.x*v1.x + v1.y*v1.y + v1.z*v1.z + v1.w*v1.w;

    __shared__ float red_s[2][4], red_q[2][4];
    for (int o = 16; o > 0; o >>= 1) {
        s  += __shfl_xor_sync(0xffffffffu, s,  o);
        sq += __shfl_xor_sync(0xffffffffu, sq, o);
    }
    int wid = t >> 5, lid = t & 31;
    if (lid == 0) { red_s[grp][wid] = s; red_q[grp][wid] = sq; }
    __syncthreads();
    float ss = red_s[grp][0] + red_s[grp][1] + red_s[grp][2] + red_s[grp][3];
    float qq = red_q[grp][0] + red_q[grp][1] + red_q[grp][2] + red_q[grp][3];

    float mean = ss * (1.0f / DMODEL);
    float var  = qq * (1.0f / DMODEL) - mean * mean;
    float rstd = rsqrtf(var + 1e-5f);

    float4 gv0 = reinterpret_cast<const float4*>(g)[t];
    float4 bv0 = reinterpret_cast<const float4*>(b)[t];
    float4 gv1 = reinterpret_cast<const float4*>(g)[t + 128];
    float4 bv1 = reinterpret_cast<const float4*>(b)[t + 128];
    float o0 = (v0.x - mean) * rstd * gv0.x + bv0.x;
    float o1 = (v0.y - mean) * rstd * gv0.y + bv0.y;
    float o2 = (v0.z - mean) * rstd * gv0.z + bv0.z;
    float o3 = (v0.w - mean) * rstd * gv0.w + bv0.w;
    float o4 = (v1.x - mean) * rstd * gv1.x + bv1.x;
    float o5 = (v1.y - mean) * rstd * gv1.y + bv1.y;
    float o6 = (v1.z - mean) * rstd * gv1.z + bv1.z;
    float o7 = (v1.w - mean) * rstd * gv1.w + bv1.w;
    __half2* ph = reinterpret_cast<__half2*>(oh + (size_t)row * DMODEL);
    ph[t*2]       = __half2(__float2half(o0), __float2half(o1));
    ph[t*2+1]     = __half2(__float2half(o2), __float2half(o3));
    ph[256 + t*2]   = __half2(__float2half(o4), __float2half(o5));
    ph[256 + t*2+1] = __half2(__float2half(o6), __float2half(o7));
}

// ---------------- CUTLASS-shape fp16 GEMM (5 stages) + smem-staged fp16 epilogue ----------------
// CTA 128x128, 4 warps (2M x 2N), warp tile 64x64, KBLK=32, 5 stages, 2 CTAs/SM.
// EPI: 0 = fp16 C; 1 = +bias +resid -> fp32 C; 2 = +bias, GELU -> fp16 C
#define KBLK 32
#define A_ST_BYTES 8192
#define STAGE_BYTES 16384
#define NSTAGE 5
#define MG_SMEM (NSTAGE * STAGE_BYTES)   // 81920
#define EPI_RS 288                       // epilogue smem row stride (256B data + 32B pad)

template<int EPI>
__global__ __launch_bounds__(128, 2)
void mma_gemm(const __half* __restrict__ A, const __half* __restrict__ B,
              const float* __restrict__ bias, const float* __restrict__ resid,
              float* __restrict__ C, __half* __restrict__ Ch,
              int M, int N, int K)
{
    extern __shared__ char sm[];
    uint32_t sb = smem_u32(sm);

    int tid  = threadIdx.x;
    int wid  = tid >> 5;
    int lane = tid & 31;
    int wm   = wid & 1;
    int wn   = wid >> 1;

    int row0 = blockIdx.y * 128, col0 = blockIdx.x * 128;
    const __half* pA = A + (size_t)row0 * K;
    const __half* pB = B + (size_t)col0 * K;

    int KB = K / KBLK;

    int ld_r[4], ld_c[4];
    uint32_t ld_so[4];
    #pragma unroll
    for (int i = 0; i < 4; i++) {
        int idx = tid + (i << 7);
        ld_r[i] = idx >> 2;
        ld_c[i] = idx & 3;
        ld_so[i] = SMEM_SWZ64((uint32_t)(ld_r[i] * 64 + ld_c[i] * 16));
    }

    auto stage_base = [&](int kb) {
        return sb + (uint32_t)(kb % NSTAGE) * STAGE_BYTES;
    };

    auto load_stage = [&](int kb) {
        uint32_t base = stage_base(kb);
        int koff = kb * KBLK;
        #pragma unroll
        for (int i = 0; i < 4; i++) {
            size_t go = (size_t)ld_r[i] * K + koff + ld_c[i] * 8;
            CP_ASYNC16(base + ld_so[i],              (const void*)(pA + go));
            CP_ASYNC16(base + A_ST_BYTES + ld_so[i], (const void*)(pB + go));
        }
        CP_COMMIT();
    };

    int a_lane_row = lane & 15;
    int a_lane_c   = (lane >> 4) << 4;
    int b_lane_row = ((lane >> 4) << 3) + (lane & 7);
    int b_lane_c   = ((lane >> 3) & 1) << 4;
    auto ld_frags = [&](uint32_t base, int kk,
                        uint32_t (*ahb)[4], uint32_t (*bhb)[2]) {
        uint32_t sA = base, sB = base + A_ST_BYTES;
        int acol = kk * 32 + a_lane_c;
        #pragma unroll
        for (int mt = 0; mt < 4; mt++) {
            int row = wm * 64 + mt * 16 + a_lane_row;
            uint32_t off = SMEM_SWZ64((uint32_t)(row * 64 + acol));
            ldsm_x4(ahb[mt], sA + off);
        }
        int bcol = kk * 32 + b_lane_c;
        #pragma unroll
        for (int p = 0; p < 4; p++) {
            int brow = wn * 64 + p * 16 + b_lane_row;
            uint32_t off = SMEM_SWZ64((uint32_t)(brow * 64 + bcol));
            uint32_t t[4];
            ldsm_x4(t, sB + off);
            bhb[p*2][0] = t[0]; bhb[p*2][1] = t[1];
            bhb[p*2+1][0] = t[2]; bhb[p*2+1][1] = t[3];
        }
    };

    float acc[4][8][4];
    #pragma unroll
    for (int i = 0; i < 4; i++)
        #pragma unroll
        for (int j = 0; j < 8; j++)
            #pragma unroll
            for (int e = 0; e < 4; e++) acc[i][j][e] = 0.f;

    #pragma unroll
    for (int s = 0; s < NSTAGE - 1; s++) load_stage(s);
    CP_WAIT(NSTAGE - 2);
    __syncthreads();

    uint32_t ah[2][4][4], bh[2][8][2];
    ld_frags(stage_base(0), 0, ah[0], bh[0]);

    for (int kb = 0; kb < KB; kb++) {
        #pragma unroll
        for (int kk = 0; kk < 2; kk++) {
            int cur = (kb * 2 + kk) & 1;
            int nxt = cur ^ 1;
            if (kk == 1) {
                if (kb + NSTAGE - 1 < KB) load_stage(kb + NSTAGE - 1);
                else                      CP_COMMIT();
                CP_WAIT(NSTAGE - 2);
                __syncthreads();
                if (kb + 1 < KB)
                    ld_frags(stage_base(kb + 1), 0, ah[nxt], bh[nxt]);
            } else {
                ld_frags(stage_base(kb), 1, ah[nxt], bh[nxt]);
            }
            #pragma unroll
            for (int mt = 0; mt < 4; mt++)
                #pragma unroll
                for (int nt = 0; nt < 8; nt++)
                    mma16816(acc[mt][nt], ah[cur][mt], bh[cur][nt]);
        }
    }

    // ---------------- epilogue ----------------
    int g  = lane >> 2;
    int c2 = (lane & 3) * 2;

    if (EPI == 1) {
        // fp32 + bias + residual (already 32B-sector efficient)
        #pragma unroll
        for (int mt = 0; mt < 4; mt++) {
            #pragma unroll
            for (int nt = 0; nt < 8; nt++) {
                int row = row0 + wm * 64 + mt * 16 + g;
                int col = col0 + wn * 64 + nt * 8 + c2;
                float d[4] = {acc[mt][nt][0], acc[mt][nt][1], acc[mt][nt][2], acc[mt][nt][3]};
                float b0 = __ldg(&bias[col]), b1 = __ldg(&bias[col + 1]);
                d[0] += b0; d[1] += b1; d[2] += b0; d[3] += b1;
                float2 r0 = *reinterpret_cast<const float2*>(&resid[(size_t)row * N + col]);
                float2 r1 = *reinterpret_cast<const float2*>(&resid[(size_t)(row + 8) * N + col]);
                d[0] += r0.x; d[1] += r0.y; d[2] += r1.x; d[3] += r1.y;
                *reinterpret_cast<float2*>(&C[(size_t)row * N + col])       = make_float2(d[0], d[1]);
                *reinterpret_cast<float2*>(&C[(size_t)(row + 8) * N + col]) = make_float2(d[2], d[3]);
            }
        }
    } else {
        // fp16 output: stage in smem (row stride EPI_RS), then coalesced uint4 stores.
        CP_WAIT(0);
        __syncthreads();       // pipeline smem fully drained; safe to reuse
        #pragma unroll
        for (int mt = 0; mt < 4; mt++) {
            #pragma unroll
            for (int nt = 0; nt < 8; nt++) {
                int rl  = wm * 64 + mt * 16 + g;        // local row
                int col = wn * 64 + nt * 8 + c2;        // local col
                float d[4] = {acc[mt][nt][0], acc[mt][nt][1], acc[mt][nt][2], acc[mt][nt][3]};
                if (EPI == 2) {
                    float b0 = __ldg(&bias[col0 + col]);
                    float b1 = __ldg(&bias[col0 + col + 1]);
                    d[0] = gelu_exact(d[0] + b0); d[1] = gelu_exact(d[1] + b1);
                    d[2] = gelu_exact(d[2] + b0); d[3] = gelu_exact(d[3] + b1);
                }
                *reinterpret_cast<__half2*>(sm + rl * EPI_RS + col * 2) =
                    __half2(__float2half(d[0]), __float2half(d[1]));
                *reinterpret_cast<__half2*>(sm + (rl + 8) * EPI_RS + col * 2) =
                    __half2(__float2half(d[2]), __float2half(d[3]));
            }
        }
        __syncthreads();
        // copy out: 128 rows x 16 chunks(16B) = 2048 = 16 iters x 128 threads
        #pragma unroll
        for (int it = 0; it < 16; it++) {
            int idx = it * 128 + tid;
            int r  = idx >> 4;         // 0..127
            int ch = idx & 15;         // 0..15 (16B chunks of a 256B row)
            uint4 v = *reinterpret_cast<const uint4*>(sm + r * EPI_RS + ch * 16);
            *reinterpret_cast<uint4*>(&Ch[(size_t)(row0 + r) * N + col0 + ch * 8]) = v;
        }
    }
}

// ---------------- tensor-core causal flash attention (fp16, exp2 softmax) ----------------
#define ATT_SMEM (8192 + 2 * 16384)   // 40960
#define SCALE_LOG2E 0.180336880f      // (1/8) * log2(e)

__global__ __launch_bounds__(128, 4)
void attn_mma(const __half* __restrict__ QKV,
              __half* __restrict__ O)
{
    extern __shared__ char sm[];
    uint32_t sb = smem_u32(sm);
    int tid = threadIdx.x, lane = tid & 31, w = tid >> 5;
    int bh = blockIdx.y, b = bh >> 4, h = bh & 15;
    int qt = gridDim.x - 1 - blockIdx.x;   // longest-first scheduling
    const int QS = QKV_N;

    {
        size_t q0 = (size_t)(b * SEQ + qt * 64) * QS + h * DK;
        #pragma unroll
        for (int i = 0; i < 4; i++) {
            int idx = tid + (i << 7);
            int r = idx >> 3, c = idx & 7;
            uint32_t so = SMEM_SWZ128((uint32_t)(r * 128 + c * 16));
            CP_ASYNC16(sb + so, (const void*)(QKV + q0 + (size_t)r * QS + c * 8));
        }
    }

    auto load_kv = [&](int kt) {
        uint32_t base = sb + 8192 + (kt & 1) * 16384;
        size_t k0 = (size_t)(b * SEQ + kt * 64) * QS + h * DK + DMODEL;
        size_t v0 = k0 + DMODEL;
        #pragma unroll
        for (int i = 0; i < 4; i++) {
            int idx = tid + (i << 7);
            int r = idx >> 3, c = idx & 7;
            uint32_t so = SMEM_SWZ128((uint32_t)(r * 128 + c * 16));
            CP_ASYNC16(base + so,        (const void*)(QKV + k0 + (size_t)r * QS + c * 8));
            CP_ASYNC16(base + 8192 + so, (const void*)(QKV + v0 + (size_t)r * QS + c * 8));
        }
        CP_COMMIT();
    };

    load_kv(0);
    CP_WAIT(0);
    __syncthreads();

    uint32_t qh[4][4];
    {
        int arow = w * 16 + (lane & 15);
        #pragma unroll
        for (int s = 0; s < 4; s++) {
            uint32_t off = SMEM_SWZ128((uint32_t)(arow * 128 + (s * 16 + ((lane >> 4) << 3)) * 2));
            ldsm_x4(qh[s], sb + off);
        }
    }

    float oacc[8][4];
    #pragma unroll
    for (int i = 0; i < 8; i++)
        #pragma unroll
        for (int e = 0; e < 4; e++) oacc[i][e] = 0.f;
    float m0 = -1e30f, m1 = -1e30f, l0 = 0.f, l1 = 0.f;

    int r0g = qt * 64 + w * 16 + (lane >> 2);
    int r1g = r0g + 8;

    for (int kt = 0; kt <= qt; kt++) {
        if (kt > 0) { CP_WAIT(0); __syncthreads(); }
        if (kt < qt) load_kv(kt + 1);

        uint32_t kbase = sb + 8192 + (kt & 1) * 16384;
        uint32_t vbase = kbase + 8192;

        float sacc[8][4];
        #pragma unroll
        for (int i = 0; i < 8; i++)
            #pragma unroll
            for (int e = 0; e < 4; e++) sacc[i][e] = 0.f;

        int b_r = ((lane >> 4) << 3) + (lane & 7);
        #pragma unroll
        for (int s = 0; s < 4; s++) {
            int b_c2 = (s * 16 + (((lane >> 3) & 1) << 3)) * 2;
            #pragma unroll
            for (int np = 0; np < 4; np++) {
                uint32_t off = SMEM_SWZ128((uint32_t)((np * 16 + b_r) * 128 + b_c2));
                uint32_t th[4];
                ldsm_x4(th, kbase + off);
                uint32_t kh0[2] = {th[0], th[1]}, kh1[2] = {th[2], th[3]};
                mma16816(sacc[2*np],   qh[s], kh0);
                mma16816(sacc[2*np+1], qh[s], kh1);
            }
        }

        #pragma unroll
        for (int nt = 0; nt < 8; nt++)
            #pragma unroll
            for (int e = 0; e < 4; e++) sacc[nt][e] *= SCALE_LOG2E;
        if (kt == qt) {
            #pragma unroll
            for (int nt = 0; nt < 8; nt++) {
                int colb = kt * 64 + nt * 8 + 2 * (lane & 3);
                #pragma unroll
                for (int e = 0; e < 2; e++) {
                    if (colb + e > r0g) sacc[nt][e]     = -1e30f;
                    if (colb + e > r1g) sacc[nt][2 + e] = -1e30f;
                }
            }
        }

        float mx0 = sacc[0][0], mx1 = sacc[0][2];
        #pragma unroll
        for (int nt = 0; nt < 8; nt++) {
            mx0 = fmaxf(mx0, fmaxf(sacc[nt][0], sacc[nt][1]));
            mx1 = fmaxf(mx1, fmaxf(sacc[nt][2], sacc[nt][3]));
        }
        mx0 = fmaxf(mx0, __shfl_xor_sync(0xffffffffu, mx0, 1));
        mx0 = fmaxf(mx0, __shfl_xor_sync(0xffffffffu, mx0, 2));
        mx1 = fmaxf(mx1, __shfl_xor_sync(0xffffffffu, mx1, 1));
        mx1 = fmaxf(mx1, __shfl_xor_sync(0xffffffffu, mx1, 2));
        float mn0 = fmaxf(m0, mx0), mn1 = fmaxf(m1, mx1);
        float a0 = exp2f(m0 - mn0), a1 = exp2f(m1 - mn1);

        float sum0 = 0.f, sum1 = 0.f;
        #pragma unroll
        for (int nt = 0; nt < 8; nt++) {
            sacc[nt][0] = exp2f(sacc[nt][0] - mn0);
            sacc[nt][1] = exp2f(sacc[nt][1] - mn0);
            sacc[nt][2] = exp2f(sacc[nt][2] - mn1);
            sacc[nt][3] = exp2f(sacc[nt][3] - mn1);
            sum0 += sacc[nt][0] + sacc[nt][1];
            sum1 += sacc[nt][2] + sacc[nt][3];
        }
        sum0 += __shfl_xor_sync(0xffffffffu, sum0, 1);
        sum0 += __shfl_xor_sync(0xffffffffu, sum0, 2);
        sum1 += __shfl_xor_sync(0xffffffffu, sum1, 1);
        sum1 += __shfl_xor_sync(0xffffffffu, sum1, 2);
        l0 = l0 * a0 + sum0;  m0 = mn0;
        l1 = l1 * a1 + sum1;  m1 = mn1;
        #pragma unroll
        for (int nt = 0; nt < 8; nt++) {
            oacc[nt][0] *= a0; oacc[nt][1] *= a0;
            oacc[nt][2] *= a1; oacc[nt][3] *= a1;
        }

        int r_in = lane & 7, sel = lane >> 3;
        #pragma unroll
        for (int s = 0; s < 4; s++) {
            uint32_t pah[4];
            #pragma unroll
            for (int half = 0; half < 2; half++) {
                float* pv = sacc[2*s + half];
                pah[half*2]   = pack2h(__float2half(pv[0]), __float2half(pv[1]));
                pah[half*2+1] = pack2h(__float2half(pv[2]), __float2half(pv[3]));
            }
            int vrow = s * 16 + (sel & 1) * 8 + r_in;
            #pragma unroll
            for (int np = 0; np < 4; np++) {
                int cb = np * 32 + (sel >> 1) * 16;
                uint32_t off = SMEM_SWZ128((uint32_t)(vrow * 128 + cb));
                uint32_t vh[4];
                ldsm_x4_t(vh, vbase + off);
                uint32_t vh0[2] = {vh[0], vh[1]}, vh1[2] = {vh[2], vh[3]};
                mma16816(oacc[2*np],   pah, vh0);
                mma16816(oacc[2*np+1], pah, vh1);
            }
        }
    }

    float inv0 = 1.0f / l0, inv1 = 1.0f / l1;
    int grow = b * SEQ + r0g;
    #pragma unroll
    for (int nt = 0; nt < 8; nt++) {
        int col = h * DK + nt * 8 + 2 * (lane & 3);
        *reinterpret_cast<__half2*>(&O[(size_t)grow * DMODEL + col]) =
            __half2(__float2half(oacc[nt][0] * inv0), __float2half(oacc[nt][1] * inv0));
        *reinterpret_cast<__half2*>(&O[(size_t)(grow + 8) * DMODEL + col]) =
            __half2(__float2half(oacc[nt][2] * inv1), __float2half(oacc[nt][3] * inv1));
    }
}

// ---------------- launch ----------------
extern "C" void kernel_launch(void* const* d_in, const int* in_sizes, int n_in,
                              void* d_out, int out_size)
{
    const float* x     = (const float*)d_in[0];
    const float* ln1_g = (const float*)d_in[1];
    const float* ln1_b = (const float*)d_in[2];
    const float* w_q   = (const float*)d_in[3];
    const float* w_k   = (const float*)d_in[4];
    const float* w_v   = (const float*)d_in[5];
    const float* w_o   = (const float*)d_in[6];
    const float* b_o   = (const float*)d_in[7];
    const float* ln2_g = (const float*)d_in[8];
    const float* ln2_b = (const float*)d_in[9];
    const float* w1    = (const float*)d_in[10];
    const float* b1    = (const float*)d_in[11];
    const float* w2    = (const float*)d_in[12];
    const float* b2    = (const float*)d_in[13];
    float* out = (float*)d_out;

    __half *h,*qkv,*att,*ffn,*wqkv,*wo,*w1t,*w2t;
    float *x1;
    cudaGetSymbolAddress((void**)&h,    g_h);
    cudaGetSymbolAddress((void**)&qkv,  g_qkv);
    cudaGetSymbolAddress((void**)&att,  g_att);
    cudaGetSymbolAddress((void**)&x1,   g_x1);
    cudaGetSymbolAddress((void**)&ffn,  g_ffn);
    cudaGetSymbolAddress((void**)&wqkv, g_wqkvT);
    cudaGetSymbolAddress((void**)&wo,   g_woT);
    cudaGetSymbolAddress((void**)&w1t,  g_w1T);
    cudaGetSymbolAddress((void**)&w2t,  g_w2T);

    cudaFuncSetAttribute(attn_mma, cudaFuncAttributeMaxDynamicSharedMemorySize, ATT_SMEM);
    cudaFuncSetAttribute(mma_gemm<0>, cudaFuncAttributeMaxDynamicSharedMemorySize, MG_SMEM);
    cudaFuncSetAttribute(mma_gemm<1>, cudaFuncAttributeMaxDynamicSharedMemorySize, MG_SMEM);
    cudaFuncSetAttribute(mma_gemm<2>, cudaFuncAttributeMaxDynamicSharedMemorySize, MG_SMEM);

    dim3 tb(32, 8);
    dim3 gP(DMODEL / 128, ROWS / 128);    // (8, 64)
    dim3 gF1(FFN_DIM / 128, ROWS / 128);  // (32, 64)

    // ---- Launch 1: ALL weight transposes+quantize ----
    {
        WArgs a;
        a.W[0] = w_q; a.T[0] = wqkv;                   a.K[0] = DMODEL;  a.N[0] = DMODEL;
        a.W[1] = w_k; a.T[1] = wqkv + DMODEL*DMODEL;   a.K[1] = DMODEL;  a.N[1] = DMODEL;
        a.W[2] = w_v; a.T[2] = wqkv + 2*DMODEL*DMODEL; a.K[2] = DMODEL;  a.N[2] = DMODEL;
        a.W[3] = w_o; a.T[3] = wo;                     a.K[3] = DMODEL;  a.N[3] = DMODEL;
        a.W[4] = w1;  a.T[4] = w1t;                    a.K[4] = DMODEL;  a.N[4] = FFN_DIM;
        a.W[5] = w2;  a.T[5] = w2t;                    a.K[5] = FFN_DIM; a.N[5] = DMODEL;
        int c = 0;
        for (int i = 0; i < 6; i++) {
            c += (a.K[i] / 64) * (a.N[i] / 32);
            a.cum[i] = c;
        }
        wsplit_all<<<a.cum[5], tb>>>(a);
    }
    // ---- Launch 2: LN1 ----
    ln_kernel<<<ROWS / 2, 256>>>(x, ln1_g, ln1_b, h);
    // ---- Launch 3: fused QKV projection -> fp16 ----
    mma_gemm<0><<<dim3(QKV_N/128, ROWS/128), 128, MG_SMEM>>>(h, wqkv,
        nullptr, nullptr, nullptr, qkv, ROWS, QKV_N, DMODEL);
    // ---- Launch 4: tensor-core attention -> fp16 ----
    attn_mma<<<dim3(SEQ / 64, BATCH * NHEAD), 128, ATT_SMEM>>>(qkv, att);
    // ---- Launch 5: O projection + bias + residual -> x1 (fp32) ----
    mma_gemm<1><<<gP, 128, MG_SMEM>>>(att, wo, b_o, x, x1, nullptr, ROWS, DMODEL, DMODEL);
    // ---- Launch 6: LN2 ----
    ln_kernel<<<ROWS / 2, 256>>>(x1, ln2_g, ln2_b, h);
    // ---- Launch 7: FFN up + GELU -> fp16 ----
    mma_gemm<2><<<gF1, 128, MG_SMEM>>>(h, w1t, b1, nullptr, nullptr, ffn, ROWS, FFN_DIM, DMODEL);
    // ---- Launch 8: FFN down + bias + residual -> out ----
    mma_gemm<1><<<gP, 128, MG_SMEM>>>(ffn, w2t, b2, x1, out, nullptr, ROWS, DMODEL, FFN_DIM);
}